// round 8
// baseline (speedup 1.0000x reference)
#include <cuda_runtime.h>
#include <cuda_bf16.h>
#include <math.h>
#include <cstdint>
#include <cstddef>

// Problem constants
#define T_LEN 2048
#define NH    32
#define HKV   8
#define HD    128
#define INNER 4096      // NH*HD
#define KVI   1024      // HKV*HD

// tcgen05 only exists in the compute_103a pass; the plain compute_103 JIT
// fallback pass compiles these as stubs (never executed on GB300).
#if defined(__CUDA_ARCH_FEAT_SM103_ALL) || defined(__CUDA_ARCH_FEAT_SM100_ALL)
#define TC_OK 1
#else
#define TC_OK 0
#endif

// ---------------------------------------------------------------------------
// Scratch (device globals: no allocation allowed)
// ---------------------------------------------------------------------------
__device__ float g_q [T_LEN * INNER];
__device__ float g_k [T_LEN * KVI];

__device__ __nv_bfloat16 g_xh [T_LEN * INNER], g_xl [T_LEN * INNER];
__device__ __nv_bfloat16 g_wqh[INNER * INNER], g_wql[INNER * INNER];
__device__ __nv_bfloat16 g_wkh[KVI  * INNER], g_wkl[KVI  * INNER];
__device__ __nv_bfloat16 g_wvh[KVI  * INNER], g_wvl[KVI  * INNER];
__device__ __nv_bfloat16 g_woh[INNER * INNER], g_wol[INNER * INNER];

__device__ __nv_bfloat16 g_qh [T_LEN * INNER], g_ql [T_LEN * INNER];
__device__ __nv_bfloat16 g_kh [T_LEN * KVI],  g_kl [T_LEN * KVI];
__device__ __nv_bfloat16 g_vth[KVI * T_LEN],  g_vtl[KVI * T_LEN];   // V^T [dim][t]
__device__ __nv_bfloat16 g_aoh[T_LEN * INNER], g_aol[T_LEN * INNER];

// ---------------------------------------------------------------------------
// PTX helpers (sm_103a)
// ---------------------------------------------------------------------------
static __device__ __forceinline__ uint32_t s2u(const void* p) {
    uint32_t a;
    asm("{ .reg .u64 t; cvta.to.shared.u64 t, %1; cvt.u32.u64 %0, t; }"
        : "=r"(a) : "l"(p));
    return a;
}
static __device__ __forceinline__ uint32_t elect1() {
    uint32_t p;
    asm volatile("{ .reg .pred p; elect.sync _|p, 0xFFFFFFFF; selp.b32 %0,1,0,p; }"
                 : "=r"(p));
    return p;
}
static __device__ __forceinline__ void mbar_init(uint32_t a, uint32_t n) {
    asm volatile("mbarrier.init.shared.b64 [%0], %1;" :: "r"(a), "r"(n) : "memory");
}
static __device__ __forceinline__ void mbar_wait(uint32_t a, uint32_t par) {
    asm volatile(
        "{\n\t.reg .pred P;\n\t"
        "LAB%=:\n\t"
        "mbarrier.try_wait.parity.acquire.cta.shared::cta.b64 P, [%0], %1, 0x989680;\n\t"
        "@P bra DONE%=;\n\t"
        "bra LAB%=;\n\t"
        "DONE%=:\n\t}"
        :: "r"(a), "r"(par) : "memory");
}
static __device__ __forceinline__ void tc_alloc(uint32_t smem_addr, uint32_t ncols) {
#if TC_OK
    asm volatile("tcgen05.alloc.cta_group::1.sync.aligned.shared::cta.b32 [%0], %1;"
                 :: "r"(smem_addr), "r"(ncols) : "memory");
#endif
}
static __device__ __forceinline__ void tc_relinq() {
#if TC_OK
    asm volatile("tcgen05.relinquish_alloc_permit.cta_group::1.sync.aligned;");
#endif
}
static __device__ __forceinline__ void tc_dealloc(uint32_t tmem, uint32_t ncols) {
#if TC_OK
    asm volatile("tcgen05.dealloc.cta_group::1.sync.aligned.b32 %0, %1;"
                 :: "r"(tmem), "r"(ncols));
#endif
}
static __device__ __forceinline__ void tc_commit(uint32_t mbar) {
#if TC_OK
    asm volatile("tcgen05.commit.cta_group::1.mbarrier::arrive::one.shared::cluster.b64 [%0];"
                 :: "r"(mbar) : "memory");
#endif
}
static __device__ __forceinline__ void tc_mma_f16_ss(uint32_t d, uint64_t ad, uint64_t bd,
                                                     uint32_t idesc, uint32_t en) {
#if TC_OK
    asm volatile(
        "{\n\t.reg .pred p;\n\t"
        "setp.ne.u32 p, %4, 0;\n\t"
        "tcgen05.mma.cta_group::1.kind::f16 [%0], %1, %2, %3, {%5,%5,%5,%5}, p;\n\t}"
        :: "r"(d), "l"(ad), "l"(bd), "r"(idesc), "r"(en), "r"(0u) : "memory");
#endif
}
static __device__ __forceinline__ void tc_mma_f16_ts(uint32_t d, uint32_t a, uint64_t bd,
                                                     uint32_t idesc, uint32_t en) {
#if TC_OK
    asm volatile(
        "{\n\t.reg .pred p;\n\t"
        "setp.ne.u32 p, %4, 0;\n\t"
        "tcgen05.mma.cta_group::1.kind::f16 [%0], [%1], %2, %3, {%5,%5,%5,%5}, p;\n\t}"
        :: "r"(d), "r"(a), "l"(bd), "r"(idesc), "r"(en), "r"(0u) : "memory");
#endif
}
static __device__ __forceinline__ void tc_waitld() {
#if TC_OK
    asm volatile("tcgen05.wait::ld.sync.aligned;" ::: "memory");
#endif
}
static __device__ __forceinline__ void tc_waitst() {
#if TC_OK
    asm volatile("tcgen05.wait::st.sync.aligned;" ::: "memory");
#endif
}
static __device__ __forceinline__ void tc_fence_after() {
#if TC_OK
    asm volatile("tcgen05.fence::after_thread_sync;" ::: "memory");
#endif
}
static __device__ __forceinline__ void tc_fence_before() {
#if TC_OK
    asm volatile("tcgen05.fence::before_thread_sync;" ::: "memory");
#endif
}
static __device__ __forceinline__ void fence_async() {
    asm volatile("fence.proxy.async.shared::cta;" ::: "memory");
}
static __device__ __forceinline__ void tc_ld32(uint32_t* r, uint32_t ta) {
#if TC_OK
    asm volatile(
        "tcgen05.ld.sync.aligned.32x32b.x32.b32 "
        "{%0, %1, %2, %3, %4, %5, %6, %7, "
        " %8, %9, %10, %11, %12, %13, %14, %15, "
        " %16, %17, %18, %19, %20, %21, %22, %23, "
        " %24, %25, %26, %27, %28, %29, %30, %31}, [%32];"
        : "=r"(r[0]),  "=r"(r[1]),  "=r"(r[2]),  "=r"(r[3]),
          "=r"(r[4]),  "=r"(r[5]),  "=r"(r[6]),  "=r"(r[7]),
          "=r"(r[8]),  "=r"(r[9]),  "=r"(r[10]), "=r"(r[11]),
          "=r"(r[12]), "=r"(r[13]), "=r"(r[14]), "=r"(r[15]),
          "=r"(r[16]), "=r"(r[17]), "=r"(r[18]), "=r"(r[19]),
          "=r"(r[20]), "=r"(r[21]), "=r"(r[22]), "=r"(r[23]),
          "=r"(r[24]), "=r"(r[25]), "=r"(r[26]), "=r"(r[27]),
          "=r"(r[28]), "=r"(r[29]), "=r"(r[30]), "=r"(r[31])
        : "r"(ta));
#else
    for (int i = 0; i < 32; i++) r[i] = 0u;
    (void)ta;
#endif
}
static __device__ __forceinline__ void tc_st16(uint32_t ta, const uint32_t* r) {
#if TC_OK
    asm volatile(
        "tcgen05.st.sync.aligned.32x32b.x16.b32 [%0], "
        "{%1, %2, %3, %4, %5, %6, %7, %8, "
        " %9, %10, %11, %12, %13, %14, %15, %16};"
        :: "r"(ta),
           "r"(r[0]),  "r"(r[1]),  "r"(r[2]),  "r"(r[3]),
           "r"(r[4]),  "r"(r[5]),  "r"(r[6]),  "r"(r[7]),
           "r"(r[8]),  "r"(r[9]),  "r"(r[10]), "r"(r[11]),
           "r"(r[12]), "r"(r[13]), "r"(r[14]), "r"(r[15])
        : "memory");
#else
    (void)ta; (void)r;
#endif
}
static __device__ __forceinline__ uint64_t mk_desc(uint32_t addr) {
    // K-major SW128: LBO=1 (16B), SBO=64 (1024B / 8-row atom)
    const uint64_t BASE = (2ull << 61) | (1ull << 46) | (64ull << 32) | (1ull << 16);
    return BASE | ((uint64_t)(addr >> 4) & 0x3FFF);
}
static __device__ __forceinline__ void cp16(uint32_t dst, const void* src) {
    asm volatile("cp.async.cg.shared.global [%0], [%1], 16;"
                 :: "r"(dst), "l"(src) : "memory");
}
static __device__ __forceinline__ void cp_commit() {
    asm volatile("cp.async.commit_group;" ::: "memory");
}
static __device__ __forceinline__ void cp_wait1() {
    asm volatile("cp.async.wait_group 1;" ::: "memory");
}
static __device__ __forceinline__ void cp_wait0() {
    asm volatile("cp.async.wait_group 0;" ::: "memory");
}
static __device__ __forceinline__ uint32_t pk2(__nv_bfloat16 a, __nv_bfloat16 b) {
    __nv_bfloat162 t(a, b);
    return *(uint32_t*)&t;
}

// ---------------------------------------------------------------------------
// fp32 -> (bf16 hi, bf16 lo)
// ---------------------------------------------------------------------------
__global__ __launch_bounds__(256) void split_kernel(
    const float* __restrict__ in, __nv_bfloat16* __restrict__ hi,
    __nv_bfloat16* __restrict__ lo, int n)
{
    int stride = gridDim.x * blockDim.x * 4;
    for (int i = (blockIdx.x * blockDim.x + threadIdx.x) * 4; i < n; i += stride) {
        float4 x = *(const float4*)(in + i);
        __nv_bfloat16 h0 = __float2bfloat16(x.x);
        __nv_bfloat16 h1 = __float2bfloat16(x.y);
        __nv_bfloat16 h2 = __float2bfloat16(x.z);
        __nv_bfloat16 h3 = __float2bfloat16(x.w);
        __nv_bfloat16 l0 = __float2bfloat16(x.x - __bfloat162float(h0));
        __nv_bfloat16 l1 = __float2bfloat16(x.y - __bfloat162float(h1));
        __nv_bfloat16 l2 = __float2bfloat16(x.z - __bfloat162float(h2));
        __nv_bfloat16 l3 = __float2bfloat16(x.w - __bfloat162float(h3));
        __nv_bfloat162* hp = (__nv_bfloat162*)(hi + i);
        __nv_bfloat162* lp = (__nv_bfloat162*)(lo + i);
        hp[0] = __nv_bfloat162(h0, h1); hp[1] = __nv_bfloat162(h2, h3);
        lp[0] = __nv_bfloat162(l0, l1); lp[1] = __nv_bfloat162(l2, l3);
    }
}

// ---------------------------------------------------------------------------
// tcgen05 bf16x3 GEMM, 128x128 tile (round-6/7 verified) — used for K, V.
// OUTB=0: fp32 C[m][n].  OUTB=2: transposed bf16 hi/lo Ct[n][m] (for V^T).
// ---------------------------------------------------------------------------
#define GCHUNK   64
#define GTILE_B  16384
#define GSTAGE_B (4 * GTILE_B)          // 65536
#define GCTRL    (3 * GSTAGE_B)         // 196608
#define GSMEM    (GCTRL + 64)

template<int OUTB>
__global__ __launch_bounds__(256) void gemm_tc_kernel(
    const __nv_bfloat16* __restrict__ Ah, const __nv_bfloat16* __restrict__ Al,
    const __nv_bfloat16* __restrict__ Bh, const __nv_bfloat16* __restrict__ Bl,
    float* __restrict__ C, __nv_bfloat16* __restrict__ Cht,
    __nv_bfloat16* __restrict__ Clt, int N, int K)
{
    extern __shared__ char sm_raw[];
    const uint32_t sb  = s2u(sm_raw);
    const int tid = threadIdx.x;
    const int wid = tid >> 5;
    const int m0  = blockIdx.y * 128;
    const int n0  = blockIdx.x * 128;

    if (wid == 0) { tc_alloc(sb + GCTRL + 32, 128); tc_relinq(); }
    if (tid == 0) {
        mbar_init(sb + GCTRL + 0, 1);
        mbar_init(sb + GCTRL + 8, 1);
        mbar_init(sb + GCTRL + 16, 1);
    }
    __syncthreads();
    uint32_t tmem;
    asm volatile("ld.shared.b32 %0, [%1];" : "=r"(tmem) : "r"(sb + GCTRL + 32));

    const uint32_t idesc = (1u << 4) | (1u << 7) | (1u << 10) |
                           ((128u / 8) << 17) | ((128u / 16) << 24);

    const int KW = K >> 3;
    const int g  = tid & 7;
    const int rb = tid >> 3;            // 0..31
    const int sc = g ^ (rb & 7);
    const size_t a4 = (((size_t)(m0 + rb) * K) >> 3) + g;
    const size_t b4 = (((size_t)(n0 + rb) * K) >> 3) + g;
    const uint4* srcs[4] = { (const uint4*)Ah, (const uint4*)Al,
                             (const uint4*)Bh, (const uint4*)Bl };
    const uint32_t dbase = sb + (rb * 8 + sc) * 16;

    const int NCH = K / GCHUNK;

    auto load_chunk = [&](int c, int s) {
        const size_t ko4 = (size_t)c * 8;
#pragma unroll
        for (int t = 0; t < 4; t++) {
            const size_t base = ((t < 2) ? a4 : b4) + ko4;
            const uint4* sp = srcs[t];
            const uint32_t d0 = dbase + s * GSTAGE_B + t * GTILE_B;
#pragma unroll
            for (int r = 0; r < 4; r++)
                cp16(d0 + r * 32 * 128, sp + base + (size_t)(32 * r) * KW);
        }
        cp_commit();
    };

    load_chunk(0, 0);
    load_chunk(1, 1);

    int par[3] = {0, 0, 0};
    for (int c = 0; c < NCH; c++) {
        const int s = c % 3;
        if (c == NCH - 1) cp_wait0(); else cp_wait1();
        __syncthreads();
        if (wid == 0 && elect1()) {
            fence_async();
            tc_fence_after();
            const uint32_t sa = sb + s * GSTAGE_B;
            const uint64_t dAh = mk_desc(sa);
            const uint64_t dAl = mk_desc(sa + GTILE_B);
            const uint64_t dBh = mk_desc(sa + 2 * GTILE_B);
            const uint64_t dBl = mk_desc(sa + 3 * GTILE_B);
#pragma unroll
            for (int ks = 0; ks < 4; ks++)
                tc_mma_f16_ss(tmem, dAh + ks * 2, dBh + ks * 2, idesc,
                              (c == 0 && ks == 0) ? 0u : 1u);
#pragma unroll
            for (int ks = 0; ks < 4; ks++)
                tc_mma_f16_ss(tmem, dAh + ks * 2, dBl + ks * 2, idesc, 1u);
#pragma unroll
            for (int ks = 0; ks < 4; ks++)
                tc_mma_f16_ss(tmem, dAl + ks * 2, dBh + ks * 2, idesc, 1u);
            tc_commit(sb + GCTRL + s * 8);
        }
        if (c + 2 < NCH) {
            if (c >= 1) {
                int ws = (c - 1) % 3;
                mbar_wait(sb + GCTRL + ws * 8, par[ws]);
                par[ws] ^= 1;
            }
            load_chunk(c + 2, (c + 2) % 3);
        }
    }

    {   // wait for the final chunk's MMAs
        int sl = (NCH - 1) % 3;
        int q  = (NCH - 1 - sl) / 3 + 1;
        mbar_wait(sb + GCTRL + sl * 8, (q - 1) & 1);
    }
    tc_fence_after();

    if (tid < 128) {
#pragma unroll
        for (int cb = 0; cb < 4; cb++) {
            uint32_t dr[32];
            tc_ld32(dr, tmem + cb * 32);
            tc_waitld();
            if (OUTB == 0) {
                float* cp = C + (size_t)(m0 + tid) * N + n0 + cb * 32;
#pragma unroll
                for (int j = 0; j < 32; j += 4)
                    *(float4*)(cp + j) = make_float4(
                        __uint_as_float(dr[j]), __uint_as_float(dr[j + 1]),
                        __uint_as_float(dr[j + 2]), __uint_as_float(dr[j + 3]));
            } else {
                // transposed bf16 hi/lo: Ct[n][m], coalesced along m (=tid)
#pragma unroll
                for (int j = 0; j < 32; j++) {
                    float f = __uint_as_float(dr[j]);
                    __nv_bfloat16 hv = __float2bfloat16(f);
                    __nv_bfloat16 lv = __float2bfloat16(f - __bfloat162float(hv));
                    size_t idx = (size_t)(n0 + cb * 32 + j) * T_LEN + m0 + tid;
                    Cht[idx] = hv;
                    Clt[idx] = lv;
                }
            }
        }
        tc_fence_before();
    }
    __syncthreads();
    if (wid == 0) tc_dealloc(tmem, 128);
}

// ---------------------------------------------------------------------------
// Wide tcgen05 bf16x3 GEMM: 128x256 tile, 2-stage pipeline — used for Q, O.
// Same verified N=128 MMA issued twice per pass (TMEM cols 0-127 / 128-255,
// B desc advanced +16KB). Halves the CTA count and cuts L2 traffic 0.75x.
// fp32 output only.
// ---------------------------------------------------------------------------
#define WTILE_A  16384                  // 128 rows x 128B (per hi/lo)
#define WTILE_B  32768                  // 256 rows x 128B (per hi/lo)
#define WSTAGE   (2 * WTILE_A + 2 * WTILE_B)   // 98304
#define WCTRL    (2 * WSTAGE)                  // 196608
#define WSMEM    (WCTRL + 64)

__global__ __launch_bounds__(256) void gemm_tc_wide_kernel(
    const __nv_bfloat16* __restrict__ Ah, const __nv_bfloat16* __restrict__ Al,
    const __nv_bfloat16* __restrict__ Bh, const __nv_bfloat16* __restrict__ Bl,
    float* __restrict__ C, int N, int K)
{
    extern __shared__ char sm_raw[];
    const uint32_t sb  = s2u(sm_raw);
    const int tid = threadIdx.x;
    const int wid = tid >> 5;
    const int m0  = blockIdx.y * 128;
    const int n0  = blockIdx.x * 256;

    if (wid == 0) { tc_alloc(sb + WCTRL + 32, 256); tc_relinq(); }
    if (tid == 0) {
        mbar_init(sb + WCTRL + 0, 1);
        mbar_init(sb + WCTRL + 8, 1);
    }
    __syncthreads();
    uint32_t tmem;
    asm volatile("ld.shared.b32 %0, [%1];" : "=r"(tmem) : "r"(sb + WCTRL + 32));

    const uint32_t idesc = (1u << 4) | (1u << 7) | (1u << 10) |
                           ((128u / 8) << 17) | ((128u / 16) << 24);

    const int KW = K >> 3;
    const int g  = tid & 7;
    const int rb = tid >> 3;            // 0..31
    const int sc = g ^ (rb & 7);
    const size_t a4 = (((size_t)(m0 + rb) * K) >> 3) + g;
    const size_t b4 = (((size_t)(n0 + rb) * K) >> 3) + g;
    const uint32_t dbase = sb + (rb * 8 + sc) * 16;

    const int NCH = K / GCHUNK;         // K64 chunks

    auto load_chunk = [&](int c, int s) {
        const size_t ko4 = (size_t)c * 8;
        const uint32_t s0 = dbase + s * WSTAGE;
        // A hi/lo: 128 rows each
#pragma unroll
        for (int t = 0; t < 2; t++) {
            const uint4* sp = (const uint4*)(t ? Al : Ah);
            const uint32_t d0 = s0 + t * WTILE_A;
#pragma unroll
            for (int r = 0; r < 4; r++)
                cp16(d0 + r * 32 * 128, sp + a4 + ko4 + (size_t)(32 * r) * KW);
        }
        // B hi/lo: 256 rows each
#pragma unroll
        for (int t = 0; t < 2; t++) {
            const uint4* sp = (const uint4*)(t ? Bl : Bh);
            const uint32_t d0 = s0 + 2 * WTILE_A + t * WTILE_B;
#pragma unroll
            for (int r = 0; r < 8; r++)
                cp16(d0 + r * 32 * 128, sp + b4 + ko4 + (size_t)(32 * r) * KW);
        }
        cp_commit();
    };

    load_chunk(0, 0);
    load_chunk(1, 1);

    int par[2] = {0, 0};
    for (int c = 0; c < NCH; c++) {
        const int s = c & 1;
        if (c == NCH - 1) cp_wait0(); else cp_wait1();
        __syncthreads();
        if (wid == 0 && elect1()) {
            fence_async();
            tc_fence_after();
            const uint32_t sa = sb + s * WSTAGE;
            const uint64_t dA[2] = { mk_desc(sa), mk_desc(sa + WTILE_A) };
            const uint64_t dB[2] = { mk_desc(sa + 2 * WTILE_A),
                                     mk_desc(sa + 2 * WTILE_A + WTILE_B) };
#pragma unroll
            for (int p = 0; p < 3; p++) {
                const int ai = (p == 2) ? 1 : 0;    // Al only on pass 2
                const int bi = (p == 1) ? 1 : 0;    // Bl only on pass 1
#pragma unroll
                for (int nb = 0; nb < 2; nb++)
#pragma unroll
                    for (int ks = 0; ks < 4; ks++)
                        tc_mma_f16_ss(tmem + nb * 128,
                                      dA[ai] + ks * 2,
                                      dB[bi] + nb * 1024 + ks * 2,   // +16KB rows
                                      idesc,
                                      (c == 0 && p == 0 && ks == 0) ? 0u : 1u);
            }
            tc_commit(sb + WCTRL + s * 8);
        }
        // wait this chunk's MMA before its stage is refilled (loads of c+1
        // are still streaming, so the load pipe never starves)
        mbar_wait(sb + WCTRL + s * 8, par[s]);
        par[s] ^= 1;
        if (c + 2 < NCH) load_chunk(c + 2, s);
    }
    tc_fence_after();

    if (tid < 128) {
#pragma unroll
        for (int cb = 0; cb < 8; cb++) {
            uint32_t dr[32];
            tc_ld32(dr, tmem + cb * 32);
            tc_waitld();
            float* cp = C + (size_t)(m0 + tid) * N + n0 + cb * 32;
#pragma unroll
            for (int j = 0; j < 32; j += 4)
                *(float4*)(cp + j) = make_float4(
                    __uint_as_float(dr[j]), __uint_as_float(dr[j + 1]),
                    __uint_as_float(dr[j + 2]), __uint_as_float(dr[j + 3]));
        }
        tc_fence_before();
    }
    __syncthreads();
    if (wid == 0) tc_dealloc(tmem, 256);
}

// ---------------------------------------------------------------------------
// RoPE -> pre-scaled bf16 hi/lo Q (x 1/sqrt(128)) and bf16 hi/lo K.
// ---------------------------------------------------------------------------
__global__ __launch_bounds__(256) void rope_kernel(
    const float* __restrict__ q, const float* __restrict__ k,
    __nv_bfloat16* __restrict__ qh, __nv_bfloat16* __restrict__ ql,
    __nv_bfloat16* __restrict__ kh, __nv_bfloat16* __restrict__ kl)
{
    __shared__ float sInv[64];
    const int t = blockIdx.x;
    if (threadIdx.x < 64)
        sInv[threadIdx.x] =
            (float)exp2(-(double)threadIdx.x * 0.20762050593045952);
    __syncthreads();
    const float SC = 0.08838834764831845f;

    for (int p = threadIdx.x; p < (NH + HKV) * 64; p += 256) {
        int d = p & 63;
        float ang = (float)t * sInv[d];
        float s, c;
        sincosf(ang, &s, &c);
        size_t off; const float* base; __nv_bfloat16 *oh, *ol; float sc2;
        if (p < NH * 64) {
            off = (size_t)t * INNER + (p >> 6) * HD;
            base = q + off; oh = qh + off; ol = ql + off; sc2 = SC;
        } else {
            int pp = p - NH * 64;
            off = (size_t)t * KVI + (pp >> 6) * HD;
            base = k + off; oh = kh + off; ol = kl + off; sc2 = 1.0f;
        }
        float x1 = base[d], x2 = base[d + 64];
        float r1 = (x1 * c - x2 * s) * sc2;
        float r2 = (x2 * c + x1 * s) * sc2;
        __nv_bfloat16 h1 = __float2bfloat16(r1);
        __nv_bfloat16 h2 = __float2bfloat16(r2);
        oh[d]      = h1;  ol[d]      = __float2bfloat16(r1 - __bfloat162float(h1));
        oh[d + 64] = h2;  ol[d + 64] = __float2bfloat16(r2 - __bfloat162float(h2));
    }
}

// ---------------------------------------------------------------------------
// tcgen05 causal flash attention (round-7 verified, unchanged).
// ---------------------------------------------------------------------------
#define ATT_Q    0
#define ATT_K    65536
#define ATT_V    131072
#define ATT_CTRL 196608
#define ATT_SMEM (ATT_CTRL + 64)

__global__ __launch_bounds__(256) void attn_tc_kernel(
    const __nv_bfloat16* __restrict__ qh, const __nv_bfloat16* __restrict__ ql,
    const __nv_bfloat16* __restrict__ kh, const __nv_bfloat16* __restrict__ kl,
    const __nv_bfloat16* __restrict__ vth, const __nv_bfloat16* __restrict__ vtl,
    __nv_bfloat16* __restrict__ aoh, __nv_bfloat16* __restrict__ aol)
{
    extern __shared__ char sm_raw[];
    const uint32_t sb = s2u(sm_raw);
    const int tid  = threadIdx.x;
    const int wid  = tid >> 5;
    const int lane = tid & 31;
    const int h    = blockIdx.y;
    const int qb   = gridDim.x - 1 - blockIdx.x;   // heavy tiles first
    const int hk   = h >> 2;
    const int q0   = qb * 128;

    const uint32_t mbarS  = sb + ATT_CTRL + 0;
    const uint32_t mbarPV = sb + ATT_CTRL + 8;

    if (wid == 0) { tc_alloc(sb + ATT_CTRL + 16, 512); tc_relinq(); }
    if (tid == 0) { mbar_init(mbarS, 1); mbar_init(mbarPV, 1); }
    __syncthreads();
    uint32_t tmem;
    asm volatile("ld.shared.b32 %0, [%1];" : "=r"(tmem) : "r"(sb + ATT_CTRL + 16));
    const uint32_t TM_S = tmem, TM_O = tmem + 128, TM_PH = tmem + 256,
                   TM_PL = tmem + 320;

    const uint32_t idescS  = (1u << 4) | (1u << 7) | (1u << 10) |
                             (16u << 17) | (8u << 24);   // M128 N128
    const uint32_t idescPV = (1u << 4) | (1u << 7) | (1u << 10) |
                             (8u << 17) | (8u << 24);    // M128 N64

    const int g   = tid & 7;
    const int rb  = tid >> 3;               // 0..31
    const int sub = wid & 3;                // TMEM subpartition
    const int cgp = wid >> 2;               // column group
    const int rloc = sub * 32 + lane;       // q row within tile

    // ---- Q tile (persistent), cp.async group: {QH c0, QH c1, QL c0, QL c1}
    {
        const size_t qrow4 = ((size_t)q0 * INNER + h * HD) >> 3;
#pragma unroll
        for (int st = 0; st < 4; st++) {
            const uint4* sp = (const uint4*)((st < 2) ? qh : ql);
            const int c = st & 1;
#pragma unroll
            for (int r = 0; r < 4; r++) {
                int row = rb + 32 * r;
                cp16(sb + ATT_Q + st * 16384 + (row * 8 + (g ^ (row & 7))) * 16,
                     sp + qrow4 + (size_t)row * (INNER / 8) + c * 8 + g);
            }
        }
        cp_commit();
    }

    float l_acc = 0.f;
    int parS = 0, parPV = 0;

    for (int kt = 0; kt <= qb; kt++) {
        const int k0 = kt * 128;
        // ---- K tile cp.async
        {
            const size_t krow4 = ((size_t)k0 * KVI + hk * HD) >> 3;
#pragma unroll
            for (int st = 0; st < 4; st++) {
                const uint4* sp = (const uint4*)((st < 2) ? kh : kl);
                const int c = st & 1;
#pragma unroll
                for (int r = 0; r < 4; r++) {
                    int row = rb + 32 * r;
                    cp16(sb + ATT_K + st * 16384 + (row * 8 + (g ^ (row & 7))) * 16,
                         sp + krow4 + (size_t)row * (KVI / 8) + c * 8 + g);
                }
            }
            cp_commit();
        }
        // ---- PV(kt-1) must finish before sV overwrite / P TMEM overwrite
        if (kt > 0) { mbar_wait(mbarPV, parPV); parPV ^= 1; }
        // ---- V^T tile cp.async: 8 subtiles [64 dims][64 keys] K-major
        {
#pragma unroll
            for (int st = 0; st < 8; st++) {
                const int hl = st >> 2, hf = (st >> 1) & 1, c = st & 1;
                const uint4* sp = (const uint4*)(hl ? vtl : vth);
                const size_t base4 =
                    (((size_t)(hk * 128 + hf * 64)) * T_LEN + k0 + c * 64) >> 3;
#pragma unroll
                for (int r = 0; r < 2; r++) {
                    int row = rb + 32 * r;
                    cp16(sb + ATT_V + st * 8192 + (row * 8 + (g ^ (row & 7))) * 16,
                         sp + base4 + (size_t)row * (T_LEN / 8) + g);
                }
            }
            cp_commit();
        }
        cp_wait1();                 // Q (first iter) + K complete; V may fly
        __syncthreads();
        // ---- S = Q' K^T (3 bf16 passes, SS K-major)
        if (wid == 0 && elect1()) {
            fence_async();
            tc_fence_after();
            uint64_t dQ[4], dK[4];
#pragma unroll
            for (int st = 0; st < 4; st++) {
                dQ[st] = mk_desc(sb + ATT_Q + st * 16384);
                dK[st] = mk_desc(sb + ATT_K + st * 16384);
            }
#pragma unroll
            for (int p = 0; p < 3; p++) {
                const int ai = (p < 2) ? 0 : 2;
                const int bi = (p == 1) ? 2 : 0;
#pragma unroll
                for (int c = 0; c < 2; c++)
#pragma unroll
                    for (int ks = 0; ks < 4; ks++)
                        tc_mma_f16_ss(TM_S, dQ[ai + c] + ks * 2, dK[bi + c] + ks * 2,
                                      idescS, (p == 0 && c == 0 && ks == 0) ? 0u : 1u);
            }
            tc_commit(mbarS);
        }
        // ---- wait S, softmax epilogue (8 warps, 2 col-chunks each)
        mbar_wait(mbarS, parS); parS ^= 1;
        tc_fence_after();
#pragma unroll
        for (int cc = 0; cc < 2; cc++) {
            const int cb = cgp * 2 + cc;
            uint32_t sr[32];
            tc_ld32(sr, TM_S + cb * 32);
            tc_waitld();
            float pr[32];
#pragma unroll
            for (int j = 0; j < 32; j++) {
                float s = __uint_as_float(sr[j]);
                int key = k0 + cb * 32 + j;
                float p = __expf(s - 8.0f);
                if (kt == qb && key > q0 + rloc) p = 0.f;
                pr[j] = p;
                l_acc += p;
            }
            uint32_t ph[16], pl[16];
#pragma unroll
            for (int m = 0; m < 16; m++) {
                float f0 = pr[2 * m], f1 = pr[2 * m + 1];
                __nv_bfloat16 h0 = __float2bfloat16(f0);
                __nv_bfloat16 h1 = __float2bfloat16(f1);
                __nv_bfloat16 l0 = __float2bfloat16(f0 - __bfloat162float(h0));
                __nv_bfloat16 l1 = __float2bfloat16(f1 - __bfloat162float(h1));
                ph[m] = pk2(h0, h1);
                pl[m] = pk2(l0, l1);
            }
            tc_st16(TM_PH + cb * 16 + ((uint32_t)sub << 21), ph);
            tc_st16(TM_PL + cb * 16 + ((uint32_t)sub << 21), pl);
        }
        tc_waitst();
        tc_fence_before();
        cp_wait0();                  // V tiles complete
        __syncthreads();             // P in TMEM + V in smem visible
        // ---- O += P V (TS-mode, K-major V^T subtiles)
        if (wid == 0 && elect1()) {
            fence_async();
            tc_fence_after();
            uint64_t dV[8];
#pragma unroll
            for (int st = 0; st < 8; st++)
                dV[st] = mk_desc(sb + ATT_V + st * 8192);
#pragma unroll
            for (int hf = 0; hf < 2; hf++) {
                const uint32_t D = TM_O + hf * 64;
#pragma unroll
                for (int p = 0; p < 3; p++) {
                    const uint32_t A = (p == 2) ? TM_PL : TM_PH;
                    const int hl = (p == 1) ? 1 : 0;
#pragma unroll
                    for (int c = 0; c < 2; c++)
#pragma unroll
                        for (int ks = 0; ks < 4; ks++)
                            tc_mma_f16_ts(D, A + 32 * c + ks * 8,
                                          dV[(hl * 2 + hf) * 2 + c] + ks * 2,
                                          idescPV,
                                          (kt == 0 && p == 0 && c == 0 && ks == 0)
                                              ? 0u : 1u);
                }
            }
            tc_commit(mbarPV);
        }
    }

    mbar_wait(mbarPV, parPV);
    tc_fence_after();

    // combine l across the two warp-groups (sK area is free)
    float* lbuf = (float*)(sm_raw + ATT_K);
    lbuf[cgp * 128 + rloc] = l_acc;
    __syncthreads();
    const float linv = 1.f / (lbuf[rloc] + lbuf[128 + rloc]);

    // O epilogue: normalize + bf16 hi/lo split
#pragma unroll
    for (int cc = 0; cc < 2; cc++) {
        const int cb = cgp * 2 + cc;
        uint32_t orr[32];
        tc_ld32(orr, TM_O + cb * 32);
        tc_waitld();
        uint32_t hv[16], lv[16];
#pragma unroll
        for (int m = 0; m < 16; m++) {
            float f0 = __uint_as_float(orr[2 * m]) * linv;
            float f1 = __uint_as_float(orr[2 * m + 1]) * linv;
            __nv_bfloat16 h0 = __float2bfloat16(f0);
            __nv_bfloat16 h1 = __float2bfloat16(f1);
            __nv_bfloat16 l0 = __float2bfloat16(f0 - __bfloat162float(h0));
            __nv_bfloat16 l1 = __float2bfloat16(f1 - __bfloat162float(h1));
            hv[m] = pk2(h0, h1);
            lv[m] = pk2(l0, l1);
        }
        uint4* hq = (uint4*)(aoh + (size_t)(q0 + rloc) * INNER + h * HD + cb * 32);
        uint4* lq = (uint4*)(aol + (size_t)(q0 + rloc) * INNER + h * HD + cb * 32);
#pragma unroll
        for (int m = 0; m < 4; m++) {
            hq[m] = *(uint4*)&hv[4 * m];
            lq[m] = *(uint4*)&lv[4 * m];
        }
    }
    tc_fence_before();
    __syncthreads();
    if (wid == 0) tc_dealloc(tmem, 512);
}

// ---------------------------------------------------------------------------
extern "C" void kernel_launch(void* const* d_in, const int* in_sizes, int n_in,
                              void* d_out, int out_size)
{
    (void)in_sizes; (void)n_in; (void)out_size;
    const float* stm = (const float*)d_in[0];
    const float* w_q = (const float*)d_in[1];
    const float* w_k = (const float*)d_in[2];
    const float* w_v = (const float*)d_in[3];
    const float* w_o = (const float*)d_in[4];
    float* out = (float*)d_out;

    float *pq, *pk;
    cudaGetSymbolAddress((void**)&pq, g_q);
    cudaGetSymbolAddress((void**)&pk, g_k);

    __nv_bfloat16 *xh, *xl, *wqh, *wql, *wkh, *wkl, *wvh, *wvl, *woh, *wol;
    __nv_bfloat16 *qhp, *qlp, *khp, *klp, *vth, *vtl, *aoh, *aol;
    cudaGetSymbolAddress((void**)&xh,  g_xh);  cudaGetSymbolAddress((void**)&xl,  g_xl);
    cudaGetSymbolAddress((void**)&wqh, g_wqh); cudaGetSymbolAddress((void**)&wql, g_wql);
    cudaGetSymbolAddress((void**)&wkh, g_wkh); cudaGetSymbolAddress((void**)&wkl, g_wkl);
    cudaGetSymbolAddress((void**)&wvh, g_wvh); cudaGetSymbolAddress((void**)&wvl, g_wvl);
    cudaGetSymbolAddress((void**)&woh, g_woh); cudaGetSymbolAddress((void**)&wol, g_wol);
    cudaGetSymbolAddress((void**)&qhp, g_qh);  cudaGetSymbolAddress((void**)&qlp, g_ql);
    cudaGetSymbolAddress((void**)&khp, g_kh);  cudaGetSymbolAddress((void**)&klp, g_kl);
    cudaGetSymbolAddress((void**)&vth, g_vth); cudaGetSymbolAddress((void**)&vtl, g_vtl);
    cudaGetSymbolAddress((void**)&aoh, g_aoh); cudaGetSymbolAddress((void**)&aol, g_aol);

    cudaFuncSetAttribute(gemm_tc_kernel<0>,
                         cudaFuncAttributeMaxDynamicSharedMemorySize, GSMEM);
    cudaFuncSetAttribute(gemm_tc_kernel<2>,
                         cudaFuncAttributeMaxDynamicSharedMemorySize, GSMEM);
    cudaFuncSetAttribute(gemm_tc_wide_kernel,
                         cudaFuncAttributeMaxDynamicSharedMemorySize, WSMEM);
    cudaFuncSetAttribute(attn_tc_kernel,
                         cudaFuncAttributeMaxDynamicSharedMemorySize, ATT_SMEM);

    split_kernel<<<4096, 256>>>(stm, xh,  xl,  T_LEN * INNER);
    split_kernel<<<4096, 256>>>(w_q, wqh, wql, INNER * INNER);
    split_kernel<<<4096, 256>>>(w_k, wkh, wkl, KVI * INNER);
    split_kernel<<<4096, 256>>>(w_v, wvh, wvl, KVI * INNER);
    split_kernel<<<4096, 256>>>(w_o, woh, wol, INNER * INNER);

    gemm_tc_wide_kernel<<<dim3(INNER / 256, T_LEN / 128), 256, WSMEM>>>(
        xh, xl, wqh, wql, pq, INNER, INNER);
    gemm_tc_kernel<0><<<dim3(KVI / 128, T_LEN / 128), 256, GSMEM>>>(
        xh, xl, wkh, wkl, pk, nullptr, nullptr, KVI, INNER);
    gemm_tc_kernel<2><<<dim3(KVI / 128, T_LEN / 128), 256, GSMEM>>>(
        xh, xl, wvh, wvl, nullptr, vth, vtl, KVI, INNER);

    rope_kernel<<<T_LEN, 256>>>(pq, pk, qhp, qlp, khp, klp);

    attn_tc_kernel<<<dim3(T_LEN / 128, NH), 256, ATT_SMEM>>>(
        qhp, qlp, khp, klp, vth, vtl, aoh, aol);

    gemm_tc_wide_kernel<<<dim3(INNER / 256, T_LEN / 128), 256, WSMEM>>>(
        aoh, aol, woh, wol, out, INNER, INNER);
}

// round 9
// speedup vs baseline: 1.0742x; 1.0742x over previous
#include <cuda_runtime.h>
#include <cuda_bf16.h>
#include <math.h>
#include <cstdint>
#include <cstddef>

// Problem constants
#define T_LEN 2048
#define NH    32
#define HKV   8
#define HD    128
#define INNER 4096      // NH*HD
#define KVI   1024      // HKV*HD

// tcgen05 only exists in the compute_103a pass; the plain compute_103 JIT
// fallback pass compiles these as stubs (never executed on GB300).
#if defined(__CUDA_ARCH_FEAT_SM103_ALL) || defined(__CUDA_ARCH_FEAT_SM100_ALL)
#define TC_OK 1
#else
#define TC_OK 0
#endif

// ---------------------------------------------------------------------------
// Scratch (device globals: no allocation allowed)
// ---------------------------------------------------------------------------
__device__ float g_q [T_LEN * INNER];
__device__ float g_k [T_LEN * KVI];

__device__ __nv_bfloat16 g_xh [T_LEN * INNER], g_xl [T_LEN * INNER];
__device__ __nv_bfloat16 g_wqh[INNER * INNER], g_wql[INNER * INNER];
__device__ __nv_bfloat16 g_wkh[KVI  * INNER], g_wkl[KVI  * INNER];
__device__ __nv_bfloat16 g_wvh[KVI  * INNER], g_wvl[KVI  * INNER];
__device__ __nv_bfloat16 g_woh[INNER * INNER], g_wol[INNER * INNER];

__device__ __nv_bfloat16 g_qh [T_LEN * INNER], g_ql [T_LEN * INNER];
__device__ __nv_bfloat16 g_kh [T_LEN * KVI],  g_kl [T_LEN * KVI];
__device__ __nv_bfloat16 g_vth[KVI * T_LEN],  g_vtl[KVI * T_LEN];   // V^T [dim][t]
__device__ __nv_bfloat16 g_aoh[T_LEN * INNER], g_aol[T_LEN * INNER];

// ---------------------------------------------------------------------------
// PTX helpers (sm_103a)
// ---------------------------------------------------------------------------
static __device__ __forceinline__ uint32_t s2u(const void* p) {
    uint32_t a;
    asm("{ .reg .u64 t; cvta.to.shared.u64 t, %1; cvt.u32.u64 %0, t; }"
        : "=r"(a) : "l"(p));
    return a;
}
static __device__ __forceinline__ uint32_t elect1() {
    uint32_t p;
    asm volatile("{ .reg .pred p; elect.sync _|p, 0xFFFFFFFF; selp.b32 %0,1,0,p; }"
                 : "=r"(p));
    return p;
}
static __device__ __forceinline__ uint32_t clus_rank() {
    uint32_t r;
    asm("mov.u32 %0, %%cluster_ctarank;" : "=r"(r));
    return r;
}
static __device__ __forceinline__ void cluster_sync() {
    asm volatile("barrier.cluster.arrive.aligned;" ::: "memory");
    asm volatile("barrier.cluster.wait.aligned;" ::: "memory");
}
static __device__ __forceinline__ void mbar_init(uint32_t a, uint32_t n) {
    asm volatile("mbarrier.init.shared.b64 [%0], %1;" :: "r"(a), "r"(n) : "memory");
}
static __device__ __forceinline__ void mbar_arrive(uint32_t a) {
    asm volatile("mbarrier.arrive.shared.b64 _, [%0];" :: "r"(a) : "memory");
}
static __device__ __forceinline__ void mbar_arrive_peer(uint32_t a, uint32_t rk) {
    asm volatile(
        "{ .reg .b32 ra; mapa.shared::cluster.u32 ra, %0, %1;\n\t"
        "mbarrier.arrive.release.cluster.shared::cluster.b64 _, [ra]; }"
        :: "r"(a), "r"(rk) : "memory");
}
static __device__ __forceinline__ void mbar_wait(uint32_t a, uint32_t par) {
    asm volatile(
        "{\n\t.reg .pred P;\n\t"
        "LAB%=:\n\t"
        "mbarrier.try_wait.parity.acquire.cta.shared::cta.b64 P, [%0], %1, 0x989680;\n\t"
        "@P bra DONE%=;\n\t"
        "bra LAB%=;\n\t"
        "DONE%=:\n\t}"
        :: "r"(a), "r"(par) : "memory");
}
static __device__ __forceinline__ void mbar_wait_cluster(uint32_t a, uint32_t par) {
    asm volatile(
        "{\n\t.reg .pred P;\n\t"
        "LAB%=:\n\t"
        "mbarrier.try_wait.parity.acquire.cluster.shared::cta.b64 P, [%0], %1, 0x989680;\n\t"
        "@P bra DONE%=;\n\t"
        "bra LAB%=;\n\t"
        "DONE%=:\n\t}"
        :: "r"(a), "r"(par) : "memory");
}
static __device__ __forceinline__ void tc_alloc(uint32_t smem_addr, uint32_t ncols) {
#if TC_OK
    asm volatile("tcgen05.alloc.cta_group::1.sync.aligned.shared::cta.b32 [%0], %1;"
                 :: "r"(smem_addr), "r"(ncols) : "memory");
#endif
}
static __device__ __forceinline__ void tc_relinq() {
#if TC_OK
    asm volatile("tcgen05.relinquish_alloc_permit.cta_group::1.sync.aligned;");
#endif
}
static __device__ __forceinline__ void tc_dealloc(uint32_t tmem, uint32_t ncols) {
#if TC_OK
    asm volatile("tcgen05.dealloc.cta_group::1.sync.aligned.b32 %0, %1;"
                 :: "r"(tmem), "r"(ncols));
#endif
}
static __device__ __forceinline__ void tc_alloc_cg2(uint32_t smem_addr, uint32_t ncols) {
#if TC_OK
    asm volatile("tcgen05.alloc.cta_group::2.sync.aligned.shared::cta.b32 [%0], %1;"
                 :: "r"(smem_addr), "r"(ncols) : "memory");
#endif
}
static __device__ __forceinline__ void tc_relinq_cg2() {
#if TC_OK
    asm volatile("tcgen05.relinquish_alloc_permit.cta_group::2.sync.aligned;");
#endif
}
static __device__ __forceinline__ void tc_dealloc_cg2(uint32_t tmem, uint32_t ncols) {
#if TC_OK
    asm volatile("tcgen05.dealloc.cta_group::2.sync.aligned.b32 %0, %1;"
                 :: "r"(tmem), "r"(ncols));
#endif
}
static __device__ __forceinline__ void tc_commit(uint32_t mbar) {
#if TC_OK
    asm volatile("tcgen05.commit.cta_group::1.mbarrier::arrive::one.shared::cluster.b64 [%0];"
                 :: "r"(mbar) : "memory");
#endif
}
static __device__ __forceinline__ void tc_commit_mc_cg2(uint32_t mbar, uint16_t mask) {
#if TC_OK
    asm volatile(
        "tcgen05.commit.cta_group::2.mbarrier::arrive::one.shared::cluster.multicast::cluster.b64 [%0], %1;"
        :: "r"(mbar), "h"(mask) : "memory");
#endif
}
static __device__ __forceinline__ void tc_mma_f16_ss(uint32_t d, uint64_t ad, uint64_t bd,
                                                     uint32_t idesc, uint32_t en) {
#if TC_OK
    asm volatile(
        "{\n\t.reg .pred p;\n\t"
        "setp.ne.u32 p, %4, 0;\n\t"
        "tcgen05.mma.cta_group::1.kind::f16 [%0], %1, %2, %3, {%5,%5,%5,%5}, p;\n\t}"
        :: "r"(d), "l"(ad), "l"(bd), "r"(idesc), "r"(en), "r"(0u) : "memory");
#endif
}
static __device__ __forceinline__ void tc_mma_f16_ss_cg2(uint32_t d, uint64_t ad, uint64_t bd,
                                                         uint32_t idesc, uint32_t en) {
#if TC_OK
    asm volatile(
        "{\n\t.reg .pred p;\n\t"
        "setp.ne.u32 p, %4, 0;\n\t"
        "tcgen05.mma.cta_group::2.kind::f16 [%0], %1, %2, %3, "
        "{%5,%5,%5,%5,%5,%5,%5,%5}, p;\n\t}"
        :: "r"(d), "l"(ad), "l"(bd), "r"(idesc), "r"(en), "r"(0u) : "memory");
#endif
}
static __device__ __forceinline__ void tc_mma_f16_ts(uint32_t d, uint32_t a, uint64_t bd,
                                                     uint32_t idesc, uint32_t en) {
#if TC_OK
    asm volatile(
        "{\n\t.reg .pred p;\n\t"
        "setp.ne.u32 p, %4, 0;\n\t"
        "tcgen05.mma.cta_group::1.kind::f16 [%0], [%1], %2, %3, {%5,%5,%5,%5}, p;\n\t}"
        :: "r"(d), "r"(a), "l"(bd), "r"(idesc), "r"(en), "r"(0u) : "memory");
#endif
}
static __device__ __forceinline__ void tc_waitld() {
#if TC_OK
    asm volatile("tcgen05.wait::ld.sync.aligned;" ::: "memory");
#endif
}
static __device__ __forceinline__ void tc_waitst() {
#if TC_OK
    asm volatile("tcgen05.wait::st.sync.aligned;" ::: "memory");
#endif
}
static __device__ __forceinline__ void tc_fence_after() {
#if TC_OK
    asm volatile("tcgen05.fence::after_thread_sync;" ::: "memory");
#endif
}
static __device__ __forceinline__ void tc_fence_before() {
#if TC_OK
    asm volatile("tcgen05.fence::before_thread_sync;" ::: "memory");
#endif
}
static __device__ __forceinline__ void fence_async() {
    asm volatile("fence.proxy.async.shared::cta;" ::: "memory");
}
static __device__ __forceinline__ void tc_ld32(uint32_t* r, uint32_t ta) {
#if TC_OK
    asm volatile(
        "tcgen05.ld.sync.aligned.32x32b.x32.b32 "
        "{%0, %1, %2, %3, %4, %5, %6, %7, "
        " %8, %9, %10, %11, %12, %13, %14, %15, "
        " %16, %17, %18, %19, %20, %21, %22, %23, "
        " %24, %25, %26, %27, %28, %29, %30, %31}, [%32];"
        : "=r"(r[0]),  "=r"(r[1]),  "=r"(r[2]),  "=r"(r[3]),
          "=r"(r[4]),  "=r"(r[5]),  "=r"(r[6]),  "=r"(r[7]),
          "=r"(r[8]),  "=r"(r[9]),  "=r"(r[10]), "=r"(r[11]),
          "=r"(r[12]), "=r"(r[13]), "=r"(r[14]), "=r"(r[15]),
          "=r"(r[16]), "=r"(r[17]), "=r"(r[18]), "=r"(r[19]),
          "=r"(r[20]), "=r"(r[21]), "=r"(r[22]), "=r"(r[23]),
          "=r"(r[24]), "=r"(r[25]), "=r"(r[26]), "=r"(r[27]),
          "=r"(r[28]), "=r"(r[29]), "=r"(r[30]), "=r"(r[31])
        : "r"(ta));
#else
    for (int i = 0; i < 32; i++) r[i] = 0u;
    (void)ta;
#endif
}
static __device__ __forceinline__ void tc_st16(uint32_t ta, const uint32_t* r) {
#if TC_OK
    asm volatile(
        "tcgen05.st.sync.aligned.32x32b.x16.b32 [%0], "
        "{%1, %2, %3, %4, %5, %6, %7, %8, "
        " %9, %10, %11, %12, %13, %14, %15, %16};"
        :: "r"(ta),
           "r"(r[0]),  "r"(r[1]),  "r"(r[2]),  "r"(r[3]),
           "r"(r[4]),  "r"(r[5]),  "r"(r[6]),  "r"(r[7]),
           "r"(r[8]),  "r"(r[9]),  "r"(r[10]), "r"(r[11]),
           "r"(r[12]), "r"(r[13]), "r"(r[14]), "r"(r[15])
        : "memory");
#else
    (void)ta; (void)r;
#endif
}
static __device__ __forceinline__ uint64_t mk_desc(uint32_t addr) {
    // K-major SW128: LBO=1 (16B), SBO=64 (1024B / 8-row atom)
    const uint64_t BASE = (2ull << 61) | (1ull << 46) | (64ull << 32) | (1ull << 16);
    return BASE | ((uint64_t)(addr >> 4) & 0x3FFF);
}
static __device__ __forceinline__ void cp16(uint32_t dst, const void* src) {
    asm volatile("cp.async.cg.shared.global [%0], [%1], 16;"
                 :: "r"(dst), "l"(src) : "memory");
}
static __device__ __forceinline__ void cp_commit() {
    asm volatile("cp.async.commit_group;" ::: "memory");
}
static __device__ __forceinline__ void cp_wait1() {
    asm volatile("cp.async.wait_group 1;" ::: "memory");
}
static __device__ __forceinline__ void cp_wait0() {
    asm volatile("cp.async.wait_group 0;" ::: "memory");
}
static __device__ __forceinline__ uint32_t pk2(__nv_bfloat16 a, __nv_bfloat16 b) {
    __nv_bfloat162 t(a, b);
    return *(uint32_t*)&t;
}

// ---------------------------------------------------------------------------
// fp32 -> (bf16 hi, bf16 lo)
// ---------------------------------------------------------------------------
__global__ __launch_bounds__(256) void split_kernel(
    const float* __restrict__ in, __nv_bfloat16* __restrict__ hi,
    __nv_bfloat16* __restrict__ lo, int n)
{
    int stride = gridDim.x * blockDim.x * 4;
    for (int i = (blockIdx.x * blockDim.x + threadIdx.x) * 4; i < n; i += stride) {
        float4 x = *(const float4*)(in + i);
        __nv_bfloat16 h0 = __float2bfloat16(x.x);
        __nv_bfloat16 h1 = __float2bfloat16(x.y);
        __nv_bfloat16 h2 = __float2bfloat16(x.z);
        __nv_bfloat16 h3 = __float2bfloat16(x.w);
        __nv_bfloat16 l0 = __float2bfloat16(x.x - __bfloat162float(h0));
        __nv_bfloat16 l1 = __float2bfloat16(x.y - __bfloat162float(h1));
        __nv_bfloat16 l2 = __float2bfloat16(x.z - __bfloat162float(h2));
        __nv_bfloat16 l3 = __float2bfloat16(x.w - __bfloat162float(h3));
        __nv_bfloat162* hp = (__nv_bfloat162*)(hi + i);
        __nv_bfloat162* lp = (__nv_bfloat162*)(lo + i);
        hp[0] = __nv_bfloat162(h0, h1); hp[1] = __nv_bfloat162(h2, h3);
        lp[0] = __nv_bfloat162(l0, l1); lp[1] = __nv_bfloat162(l2, l3);
    }
}

// ---------------------------------------------------------------------------
// tcgen05 bf16x3 GEMM, 128x128 tile (round-6/7 verified) — used for K, V.
// OUTB=0: fp32 C[m][n].  OUTB=2: transposed bf16 hi/lo Ct[n][m] (for V^T).
// ---------------------------------------------------------------------------
#define GCHUNK   64
#define GTILE_B  16384
#define GSTAGE_B (4 * GTILE_B)          // 65536
#define GCTRL    (3 * GSTAGE_B)         // 196608
#define GSMEM    (GCTRL + 64)

template<int OUTB>
__global__ __launch_bounds__(256) void gemm_tc_kernel(
    const __nv_bfloat16* __restrict__ Ah, const __nv_bfloat16* __restrict__ Al,
    const __nv_bfloat16* __restrict__ Bh, const __nv_bfloat16* __restrict__ Bl,
    float* __restrict__ C, __nv_bfloat16* __restrict__ Cht,
    __nv_bfloat16* __restrict__ Clt, int N, int K)
{
    extern __shared__ char sm_raw[];
    const uint32_t sb  = s2u(sm_raw);
    const int tid = threadIdx.x;
    const int wid = tid >> 5;
    const int m0  = blockIdx.y * 128;
    const int n0  = blockIdx.x * 128;

    if (wid == 0) { tc_alloc(sb + GCTRL + 32, 128); tc_relinq(); }
    if (tid == 0) {
        mbar_init(sb + GCTRL + 0, 1);
        mbar_init(sb + GCTRL + 8, 1);
        mbar_init(sb + GCTRL + 16, 1);
    }
    __syncthreads();
    uint32_t tmem;
    asm volatile("ld.shared.b32 %0, [%1];" : "=r"(tmem) : "r"(sb + GCTRL + 32));

    const uint32_t idesc = (1u << 4) | (1u << 7) | (1u << 10) |
                           ((128u / 8) << 17) | ((128u / 16) << 24);

    const int KW = K >> 3;
    const int g  = tid & 7;
    const int rb = tid >> 3;            // 0..31
    const int sc = g ^ (rb & 7);
    const size_t a4 = (((size_t)(m0 + rb) * K) >> 3) + g;
    const size_t b4 = (((size_t)(n0 + rb) * K) >> 3) + g;
    const uint4* srcs[4] = { (const uint4*)Ah, (const uint4*)Al,
                             (const uint4*)Bh, (const uint4*)Bl };
    const uint32_t dbase = sb + (rb * 8 + sc) * 16;

    const int NCH = K / GCHUNK;

    auto load_chunk = [&](int c, int s) {
        const size_t ko4 = (size_t)c * 8;
#pragma unroll
        for (int t = 0; t < 4; t++) {
            const size_t base = ((t < 2) ? a4 : b4) + ko4;
            const uint4* sp = srcs[t];
            const uint32_t d0 = dbase + s * GSTAGE_B + t * GTILE_B;
#pragma unroll
            for (int r = 0; r < 4; r++)
                cp16(d0 + r * 32 * 128, sp + base + (size_t)(32 * r) * KW);
        }
        cp_commit();
    };

    load_chunk(0, 0);
    load_chunk(1, 1);

    int par[3] = {0, 0, 0};
    for (int c = 0; c < NCH; c++) {
        const int s = c % 3;
        if (c == NCH - 1) cp_wait0(); else cp_wait1();
        __syncthreads();
        if (wid == 0 && elect1()) {
            fence_async();
            tc_fence_after();
            const uint32_t sa = sb + s * GSTAGE_B;
            const uint64_t dAh = mk_desc(sa);
            const uint64_t dAl = mk_desc(sa + GTILE_B);
            const uint64_t dBh = mk_desc(sa + 2 * GTILE_B);
            const uint64_t dBl = mk_desc(sa + 3 * GTILE_B);
#pragma unroll
            for (int ks = 0; ks < 4; ks++)
                tc_mma_f16_ss(tmem, dAh + ks * 2, dBh + ks * 2, idesc,
                              (c == 0 && ks == 0) ? 0u : 1u);
#pragma unroll
            for (int ks = 0; ks < 4; ks++)
                tc_mma_f16_ss(tmem, dAh + ks * 2, dBl + ks * 2, idesc, 1u);
#pragma unroll
            for (int ks = 0; ks < 4; ks++)
                tc_mma_f16_ss(tmem, dAl + ks * 2, dBh + ks * 2, idesc, 1u);
            tc_commit(sb + GCTRL + s * 8);
        }
        if (c + 2 < NCH) {
            if (c >= 1) {
                int ws = (c - 1) % 3;
                mbar_wait(sb + GCTRL + ws * 8, par[ws]);
                par[ws] ^= 1;
            }
            load_chunk(c + 2, (c + 2) % 3);
        }
    }

    {   // wait for the final chunk's MMAs
        int sl = (NCH - 1) % 3;
        int q  = (NCH - 1 - sl) / 3 + 1;
        mbar_wait(sb + GCTRL + sl * 8, (q - 1) & 1);
    }
    tc_fence_after();

    if (tid < 128) {
#pragma unroll
        for (int cb = 0; cb < 4; cb++) {
            uint32_t dr[32];
            tc_ld32(dr, tmem + cb * 32);
            tc_waitld();
            if (OUTB == 0) {
                float* cp = C + (size_t)(m0 + tid) * N + n0 + cb * 32;
#pragma unroll
                for (int j = 0; j < 32; j += 4)
                    *(float4*)(cp + j) = make_float4(
                        __uint_as_float(dr[j]), __uint_as_float(dr[j + 1]),
                        __uint_as_float(dr[j + 2]), __uint_as_float(dr[j + 3]));
            } else {
                // transposed bf16 hi/lo: Ct[n][m], coalesced along m (=tid)
#pragma unroll
                for (int j = 0; j < 32; j++) {
                    float f = __uint_as_float(dr[j]);
                    __nv_bfloat16 hv = __float2bfloat16(f);
                    __nv_bfloat16 lv = __float2bfloat16(f - __bfloat162float(hv));
                    size_t idx = (size_t)(n0 + cb * 32 + j) * T_LEN + m0 + tid;
                    Cht[idx] = hv;
                    Clt[idx] = lv;
                }
            }
        }
        tc_fence_before();
    }
    __syncthreads();
    if (wid == 0) tc_dealloc(tmem, 128);
}

// ---------------------------------------------------------------------------
// cg2 bf16x3 GEMM: 256x128 tile across a 2-CTA cluster, 3-stage pipeline.
// Each CTA loads its 128 A-rows (hi/lo) + its 64 B-rows (hi/lo) = 48KB/stage.
// Rank0 issues cta_group::2 MMAs after a per-stage "ready" mbar (count=2,
// rank1 arrives via mapa); multicast commit gates stage reuse on both CTAs.
// Used for the big Q and O projections.  fp32 output.
// ---------------------------------------------------------------------------
#define C2_TILE_A 16384                 // 128 rows x 128B
#define C2_TILE_B 8192                  // 64 rows x 128B
#define C2_STAGE  (2 * C2_TILE_A + 2 * C2_TILE_B)   // 49152
#define C2_CTRL   (3 * C2_STAGE)                    // 147456
#define C2_SMEM   (C2_CTRL + 64)

__global__ __launch_bounds__(256) __cluster_dims__(2, 1, 1)
void gemm_tc_cg2_kernel(
    const __nv_bfloat16* __restrict__ Ah, const __nv_bfloat16* __restrict__ Al,
    const __nv_bfloat16* __restrict__ Bh, const __nv_bfloat16* __restrict__ Bl,
    float* __restrict__ C, int N, int K)
{
    extern __shared__ char sm_raw[];
    const uint32_t sb  = s2u(sm_raw);
    const int tid  = threadIdx.x;
    const int wid  = tid >> 5;
    const uint32_t rank = clus_rank();
    const int m0   = (blockIdx.x >> 1) * 256 + (int)rank * 128;  // this CTA's rows
    const int n0   = blockIdx.y * 128;

    const uint32_t stage_mb = sb + C2_CTRL;        // 3 x 8B (MMA-done, multicast)
    const uint32_t ready_mb = sb + C2_CTRL + 24;   // 3 x 8B (tiles ready, count 2)
    const uint32_t tmem_ptr = sb + C2_CTRL + 48;

    if (wid == 0) tc_alloc_cg2(tmem_ptr, 128);
    if (tid == 0) {
#pragma unroll
        for (int s = 0; s < 3; s++) {
            mbar_init(stage_mb + s * 8, 1);
            mbar_init(ready_mb + s * 8, 2);
        }
    }
    __syncthreads();
    cluster_sync();                 // mbars + alloc visible cluster-wide
    uint32_t tmem;
    asm volatile("ld.shared.b32 %0, [%1];" : "=r"(tmem) : "r"(tmem_ptr));

    // idesc: F32 accum, bf16 x bf16, N=128, M_total=256 (cg2)
    const uint32_t idesc = (1u << 4) | (1u << 7) | (1u << 10) |
                           (16u << 17) | (16u << 24);

    const int KW = K >> 3;
    const int g  = tid & 7;
    const int rb = tid >> 3;            // 0..31
    const int sc = g ^ (rb & 7);
    const size_t a4 = (((size_t)(m0 + rb) * K) >> 3) + g;                // own A rows
    const size_t b4 = (((size_t)(n0 + (int)rank * 64 + rb) * K) >> 3) + g; // own B half
    const uint32_t dbase = sb + (rb * 8 + sc) * 16;

    const int NCH = K / GCHUNK;

    auto load_chunk = [&](int c, int s) {
        const size_t ko4 = (size_t)c * 8;
        const uint32_t s0 = dbase + s * C2_STAGE;
#pragma unroll
        for (int t = 0; t < 2; t++) {           // A hi/lo: 128 rows
            const uint4* sp = (const uint4*)(t ? Al : Ah);
            const uint32_t d0 = s0 + t * C2_TILE_A;
#pragma unroll
            for (int r = 0; r < 4; r++)
                cp16(d0 + r * 32 * 128, sp + a4 + ko4 + (size_t)(32 * r) * KW);
        }
#pragma unroll
        for (int t = 0; t < 2; t++) {           // B hi/lo: 64 rows (own half)
            const uint4* sp = (const uint4*)(t ? Bl : Bh);
            const uint32_t d0 = s0 + 2 * C2_TILE_A + t * C2_TILE_B;
            if (rb < 32)                         // 32 rows per pass x2 -> 64
                cp16(d0, sp + b4 + ko4);
            cp16(d0 + 32 * 128, sp + b4 + ko4 + (size_t)32 * KW);
        }
        cp_commit();
    };

    load_chunk(0, 0);
    load_chunk(1, 1);

    int par[3]    = {0, 0, 0};
    int pready[3] = {0, 0, 0};
    for (int c = 0; c < NCH; c++) {
        const int s = c % 3;
        if (c == NCH - 1) cp_wait0(); else cp_wait1();
        __syncthreads();
        if (tid == 0) {                 // signal: this CTA's stage-s tiles ready
            fence_async();
            if (rank == 0) mbar_arrive(ready_mb + s * 8);
            else           mbar_arrive_peer(ready_mb + s * 8, 0);
        }
        if (rank == 0 && wid == 0 && elect1()) {
            mbar_wait_cluster(ready_mb + s * 8, pready[s]);
            pready[s] ^= 1;
            tc_fence_after();
            const uint32_t sa = sb + s * C2_STAGE;
            const uint64_t dAh = mk_desc(sa);
            const uint64_t dAl = mk_desc(sa + C2_TILE_A);
            const uint64_t dBh = mk_desc(sa + 2 * C2_TILE_A);
            const uint64_t dBl = mk_desc(sa + 2 * C2_TILE_A + C2_TILE_B);
#pragma unroll
            for (int ks = 0; ks < 4; ks++)
                tc_mma_f16_ss_cg2(tmem, dAh + ks * 2, dBh + ks * 2, idesc,
                                  (c == 0 && ks == 0) ? 0u : 1u);
#pragma unroll
            for (int ks = 0; ks < 4; ks++)
                tc_mma_f16_ss_cg2(tmem, dAh + ks * 2, dBl + ks * 2, idesc, 1u);
#pragma unroll
            for (int ks = 0; ks < 4; ks++)
                tc_mma_f16_ss_cg2(tmem, dAl + ks * 2, dBh + ks * 2, idesc, 1u);
            tc_commit_mc_cg2(stage_mb + s * 8, 0x3);
        }
        if (c + 2 < NCH) {
            if (c >= 1) {
                int ws = (c - 1) % 3;
                mbar_wait(stage_mb + ws * 8, par[ws]);
                par[ws] ^= 1;
            }
            load_chunk(c + 2, (c + 2) % 3);
        }
    }

    {   // wait for the final chunk's MMAs (commit tracks ALL prior MMAs)
        int sl = (NCH - 1) % 3;
        int q  = (NCH - 1 - sl) / 3 + 1;
        mbar_wait(stage_mb + sl * 8, (q - 1) & 1);
    }
    tc_fence_after();

    if (tid < 128) {                    // each CTA writes its own 128 rows
#pragma unroll
        for (int cb = 0; cb < 4; cb++) {
            uint32_t dr[32];
            tc_ld32(dr, tmem + cb * 32);
            tc_waitld();
            float* cp = C + (size_t)(m0 + tid) * N + n0 + cb * 32;
#pragma unroll
            for (int j = 0; j < 32; j += 4)
                *(float4*)(cp + j) = make_float4(
                    __uint_as_float(dr[j]), __uint_as_float(dr[j + 1]),
                    __uint_as_float(dr[j + 2]), __uint_as_float(dr[j + 3]));
        }
        tc_fence_before();
    }
    __syncthreads();
    cluster_sync();                     // peer MMA reads of our smem done
    if (wid == 0) { tc_relinq_cg2(); tc_dealloc_cg2(tmem, 128); }
    cluster_sync();
}

// ---------------------------------------------------------------------------
// RoPE -> pre-scaled bf16 hi/lo Q (x 1/sqrt(128)) and bf16 hi/lo K.
// ---------------------------------------------------------------------------
__global__ __launch_bounds__(256) void rope_kernel(
    const float* __restrict__ q, const float* __restrict__ k,
    __nv_bfloat16* __restrict__ qh, __nv_bfloat16* __restrict__ ql,
    __nv_bfloat16* __restrict__ kh, __nv_bfloat16* __restrict__ kl)
{
    __shared__ float sInv[64];
    const int t = blockIdx.x;
    if (threadIdx.x < 64)
        sInv[threadIdx.x] =
            (float)exp2(-(double)threadIdx.x * 0.20762050593045952);
    __syncthreads();
    const float SC = 0.08838834764831845f;

    for (int p = threadIdx.x; p < (NH + HKV) * 64; p += 256) {
        int d = p & 63;
        float ang = (float)t * sInv[d];
        float s, c;
        sincosf(ang, &s, &c);
        size_t off; const float* base; __nv_bfloat16 *oh, *ol; float sc2;
        if (p < NH * 64) {
            off = (size_t)t * INNER + (p >> 6) * HD;
            base = q + off; oh = qh + off; ol = ql + off; sc2 = SC;
        } else {
            int pp = p - NH * 64;
            off = (size_t)t * KVI + (pp >> 6) * HD;
            base = k + off; oh = kh + off; ol = kl + off; sc2 = 1.0f;
        }
        float x1 = base[d], x2 = base[d + 64];
        float r1 = (x1 * c - x2 * s) * sc2;
        float r2 = (x2 * c + x1 * s) * sc2;
        __nv_bfloat16 h1 = __float2bfloat16(r1);
        __nv_bfloat16 h2 = __float2bfloat16(r2);
        oh[d]      = h1;  ol[d]      = __float2bfloat16(r1 - __bfloat162float(h1));
        oh[d + 64] = h2;  ol[d + 64] = __float2bfloat16(r2 - __bfloat162float(h2));
    }
}

// ---------------------------------------------------------------------------
// tcgen05 causal flash attention (round-7 verified, unchanged).
// ---------------------------------------------------------------------------
#define ATT_Q    0
#define ATT_K    65536
#define ATT_V    131072
#define ATT_CTRL 196608
#define ATT_SMEM (ATT_CTRL + 64)

__global__ __launch_bounds__(256) void attn_tc_kernel(
    const __nv_bfloat16* __restrict__ qh, const __nv_bfloat16* __restrict__ ql,
    const __nv_bfloat16* __restrict__ kh, const __nv_bfloat16* __restrict__ kl,
    const __nv_bfloat16* __restrict__ vth, const __nv_bfloat16* __restrict__ vtl,
    __nv_bfloat16* __restrict__ aoh, __nv_bfloat16* __restrict__ aol)
{
    extern __shared__ char sm_raw[];
    const uint32_t sb = s2u(sm_raw);
    const int tid  = threadIdx.x;
    const int wid  = tid >> 5;
    const int lane = tid & 31;
    const int h    = blockIdx.y;
    const int qb   = gridDim.x - 1 - blockIdx.x;   // heavy tiles first
    const int hk   = h >> 2;
    const int q0   = qb * 128;

    const uint32_t mbarS  = sb + ATT_CTRL + 0;
    const uint32_t mbarPV = sb + ATT_CTRL + 8;

    if (wid == 0) { tc_alloc(sb + ATT_CTRL + 16, 512); tc_relinq(); }
    if (tid == 0) { mbar_init(mbarS, 1); mbar_init(mbarPV, 1); }
    __syncthreads();
    uint32_t tmem;
    asm volatile("ld.shared.b32 %0, [%1];" : "=r"(tmem) : "r"(sb + ATT_CTRL + 16));
    const uint32_t TM_S = tmem, TM_O = tmem + 128, TM_PH = tmem + 256,
                   TM_PL = tmem + 320;

    const uint32_t idescS  = (1u << 4) | (1u << 7) | (1u << 10) |
                             (16u << 17) | (8u << 24);   // M128 N128
    const uint32_t idescPV = (1u << 4) | (1u << 7) | (1u << 10) |
                             (8u << 17) | (8u << 24);    // M128 N64

    const int g   = tid & 7;
    const int rb  = tid >> 3;               // 0..31
    const int sub = wid & 3;                // TMEM subpartition
    const int cgp = wid >> 2;               // column group
    const int rloc = sub * 32 + lane;       // q row within tile

    // ---- Q tile (persistent), cp.async group: {QH c0, QH c1, QL c0, QL c1}
    {
        const size_t qrow4 = ((size_t)q0 * INNER + h * HD) >> 3;
#pragma unroll
        for (int st = 0; st < 4; st++) {
            const uint4* sp = (const uint4*)((st < 2) ? qh : ql);
            const int c = st & 1;
#pragma unroll
            for (int r = 0; r < 4; r++) {
                int row = rb + 32 * r;
                cp16(sb + ATT_Q + st * 16384 + (row * 8 + (g ^ (row & 7))) * 16,
                     sp + qrow4 + (size_t)row * (INNER / 8) + c * 8 + g);
            }
        }
        cp_commit();
    }

    float l_acc = 0.f;
    int parS = 0, parPV = 0;

    for (int kt = 0; kt <= qb; kt++) {
        const int k0 = kt * 128;
        // ---- K tile cp.async
        {
            const size_t krow4 = ((size_t)k0 * KVI + hk * HD) >> 3;
#pragma unroll
            for (int st = 0; st < 4; st++) {
                const uint4* sp = (const uint4*)((st < 2) ? kh : kl);
                const int c = st & 1;
#pragma unroll
                for (int r = 0; r < 4; r++) {
                    int row = rb + 32 * r;
                    cp16(sb + ATT_K + st * 16384 + (row * 8 + (g ^ (row & 7))) * 16,
                         sp + krow4 + (size_t)row * (KVI / 8) + c * 8 + g);
                }
            }
            cp_commit();
        }
        // ---- PV(kt-1) must finish before sV overwrite / P TMEM overwrite
        if (kt > 0) { mbar_wait(mbarPV, parPV); parPV ^= 1; }
        // ---- V^T tile cp.async: 8 subtiles [64 dims][64 keys] K-major
        {
#pragma unroll
            for (int st = 0; st < 8; st++) {
                const int hl = st >> 2, hf = (st >> 1) & 1, c = st & 1;
                const uint4* sp = (const uint4*)(hl ? vtl : vth);
                const size_t base4 =
                    (((size_t)(hk * 128 + hf * 64)) * T_LEN + k0 + c * 64) >> 3;
#pragma unroll
                for (int r = 0; r < 2; r++) {
                    int row = rb + 32 * r;
                    cp16(sb + ATT_V + st * 8192 + (row * 8 + (g ^ (row & 7))) * 16,
                         sp + base4 + (size_t)row * (T_LEN / 8) + g);
                }
            }
            cp_commit();
        }
        cp_wait1();                 // Q (first iter) + K complete; V may fly
        __syncthreads();
        // ---- S = Q' K^T (3 bf16 passes, SS K-major)
        if (wid == 0 && elect1()) {
            fence_async();
            tc_fence_after();
            uint64_t dQ[4], dK[4];
#pragma unroll
            for (int st = 0; st < 4; st++) {
                dQ[st] = mk_desc(sb + ATT_Q + st * 16384);
                dK[st] = mk_desc(sb + ATT_K + st * 16384);
            }
#pragma unroll
            for (int p = 0; p < 3; p++) {
                const int ai = (p < 2) ? 0 : 2;
                const int bi = (p == 1) ? 2 : 0;
#pragma unroll
                for (int c = 0; c < 2; c++)
#pragma unroll
                    for (int ks = 0; ks < 4; ks++)
                        tc_mma_f16_ss(TM_S, dQ[ai + c] + ks * 2, dK[bi + c] + ks * 2,
                                      idescS, (p == 0 && c == 0 && ks == 0) ? 0u : 1u);
            }
            tc_commit(mbarS);
        }
        // ---- wait S, softmax epilogue (8 warps, 2 col-chunks each)
        mbar_wait(mbarS, parS); parS ^= 1;
        tc_fence_after();
#pragma unroll
        for (int cc = 0; cc < 2; cc++) {
            const int cb = cgp * 2 + cc;
            uint32_t sr[32];
            tc_ld32(sr, TM_S + cb * 32);
            tc_waitld();
            float pr[32];
#pragma unroll
            for (int j = 0; j < 32; j++) {
                float s = __uint_as_float(sr[j]);
                int key = k0 + cb * 32 + j;
                float p = __expf(s - 8.0f);
                if (kt == qb && key > q0 + rloc) p = 0.f;
                pr[j] = p;
                l_acc += p;
            }
            uint32_t ph[16], pl[16];
#pragma unroll
            for (int m = 0; m < 16; m++) {
                float f0 = pr[2 * m], f1 = pr[2 * m + 1];
                __nv_bfloat16 h0 = __float2bfloat16(f0);
                __nv_bfloat16 h1 = __float2bfloat16(f1);
                __nv_bfloat16 l0 = __float2bfloat16(f0 - __bfloat162float(h0));
                __nv_bfloat16 l1 = __float2bfloat16(f1 - __bfloat162float(h1));
                ph[m] = pk2(h0, h1);
                pl[m] = pk2(l0, l1);
            }
            tc_st16(TM_PH + cb * 16 + ((uint32_t)sub << 21), ph);
            tc_st16(TM_PL + cb * 16 + ((uint32_t)sub << 21), pl);
        }
        tc_waitst();
        tc_fence_before();
        cp_wait0();                  // V tiles complete
        __syncthreads();             // P in TMEM + V in smem visible
        // ---- O += P V (TS-mode, K-major V^T subtiles)
        if (wid == 0 && elect1()) {
            fence_async();
            tc_fence_after();
            uint64_t dV[8];
#pragma unroll
            for (int st = 0; st < 8; st++)
                dV[st] = mk_desc(sb + ATT_V + st * 8192);
#pragma unroll
            for (int hf = 0; hf < 2; hf++) {
                const uint32_t D = TM_O + hf * 64;
#pragma unroll
                for (int p = 0; p < 3; p++) {
                    const uint32_t A = (p == 2) ? TM_PL : TM_PH;
                    const int hl = (p == 1) ? 1 : 0;
#pragma unroll
                    for (int c = 0; c < 2; c++)
#pragma unroll
                        for (int ks = 0; ks < 4; ks++)
                            tc_mma_f16_ts(D, A + 32 * c + ks * 8,
                                          dV[(hl * 2 + hf) * 2 + c] + ks * 2,
                                          idescPV,
                                          (kt == 0 && p == 0 && c == 0 && ks == 0)
                                              ? 0u : 1u);
                }
            }
            tc_commit(mbarPV);
        }
    }

    mbar_wait(mbarPV, parPV);
    tc_fence_after();

    // combine l across the two warp-groups (sK area is free)
    float* lbuf = (float*)(sm_raw + ATT_K);
    lbuf[cgp * 128 + rloc] = l_acc;
    __syncthreads();
    const float linv = 1.f / (lbuf[rloc] + lbuf[128 + rloc]);

    // O epilogue: normalize + bf16 hi/lo split
#pragma unroll
    for (int cc = 0; cc < 2; cc++) {
        const int cb = cgp * 2 + cc;
        uint32_t orr[32];
        tc_ld32(orr, TM_O + cb * 32);
        tc_waitld();
        uint32_t hv[16], lv[16];
#pragma unroll
        for (int m = 0; m < 16; m++) {
            float f0 = __uint_as_float(orr[2 * m]) * linv;
            float f1 = __uint_as_float(orr[2 * m + 1]) * linv;
            __nv_bfloat16 h0 = __float2bfloat16(f0);
            __nv_bfloat16 h1 = __float2bfloat16(f1);
            __nv_bfloat16 l0 = __float2bfloat16(f0 - __bfloat162float(h0));
            __nv_bfloat16 l1 = __float2bfloat16(f1 - __bfloat162float(h1));
            hv[m] = pk2(h0, h1);
            lv[m] = pk2(l0, l1);
        }
        uint4* hq = (uint4*)(aoh + (size_t)(q0 + rloc) * INNER + h * HD + cb * 32);
        uint4* lq = (uint4*)(aol + (size_t)(q0 + rloc) * INNER + h * HD + cb * 32);
#pragma unroll
        for (int m = 0; m < 4; m++) {
            hq[m] = *(uint4*)&hv[4 * m];
            lq[m] = *(uint4*)&lv[4 * m];
        }
    }
    tc_fence_before();
    __syncthreads();
    if (wid == 0) tc_dealloc(tmem, 512);
}

// ---------------------------------------------------------------------------
extern "C" void kernel_launch(void* const* d_in, const int* in_sizes, int n_in,
                              void* d_out, int out_size)
{
    (void)in_sizes; (void)n_in; (void)out_size;
    const float* stm = (const float*)d_in[0];
    const float* w_q = (const float*)d_in[1];
    const float* w_k = (const float*)d_in[2];
    const float* w_v = (const float*)d_in[3];
    const float* w_o = (const float*)d_in[4];
    float* out = (float*)d_out;

    float *pq, *pk;
    cudaGetSymbolAddress((void**)&pq, g_q);
    cudaGetSymbolAddress((void**)&pk, g_k);

    __nv_bfloat16 *xh, *xl, *wqh, *wql, *wkh, *wkl, *wvh, *wvl, *woh, *wol;
    __nv_bfloat16 *qhp, *qlp, *khp, *klp, *vth, *vtl, *aoh, *aol;
    cudaGetSymbolAddress((void**)&xh,  g_xh);  cudaGetSymbolAddress((void**)&xl,  g_xl);
    cudaGetSymbolAddress((void**)&wqh, g_wqh); cudaGetSymbolAddress((void**)&wql, g_wql);
    cudaGetSymbolAddress((void**)&wkh, g_wkh); cudaGetSymbolAddress((void**)&wkl, g_wkl);
    cudaGetSymbolAddress((void**)&wvh, g_wvh); cudaGetSymbolAddress((void**)&wvl, g_wvl);
    cudaGetSymbolAddress((void**)&woh, g_woh); cudaGetSymbolAddress((void**)&wol, g_wol);
    cudaGetSymbolAddress((void**)&qhp, g_qh);  cudaGetSymbolAddress((void**)&qlp, g_ql);
    cudaGetSymbolAddress((void**)&khp, g_kh);  cudaGetSymbolAddress((void**)&klp, g_kl);
    cudaGetSymbolAddress((void**)&vth, g_vth); cudaGetSymbolAddress((void**)&vtl, g_vtl);
    cudaGetSymbolAddress((void**)&aoh, g_aoh); cudaGetSymbolAddress((void**)&aol, g_aol);

    cudaFuncSetAttribute(gemm_tc_kernel<0>,
                         cudaFuncAttributeMaxDynamicSharedMemorySize, GSMEM);
    cudaFuncSetAttribute(gemm_tc_kernel<2>,
                         cudaFuncAttributeMaxDynamicSharedMemorySize, GSMEM);
    cudaFuncSetAttribute(gemm_tc_cg2_kernel,
                         cudaFuncAttributeMaxDynamicSharedMemorySize, C2_SMEM);
    cudaFuncSetAttribute(attn_tc_kernel,
                         cudaFuncAttributeMaxDynamicSharedMemorySize, ATT_SMEM);

    split_kernel<<<4096, 256>>>(stm, xh,  xl,  T_LEN * INNER);
    split_kernel<<<4096, 256>>>(w_q, wqh, wql, INNER * INNER);
    split_kernel<<<4096, 256>>>(w_k, wkh, wkl, KVI * INNER);
    split_kernel<<<4096, 256>>>(w_v, wvh, wvl, KVI * INNER);
    split_kernel<<<4096, 256>>>(w_o, woh, wol, INNER * INNER);

    // Q projection: cg2 256x128 tiles (grid.x carries the 2-CTA clusters)
    gemm_tc_cg2_kernel<<<dim3((T_LEN / 256) * 2, INNER / 128), 256, C2_SMEM>>>(
        xh, xl, wqh, wql, pq, INNER, INNER);
    gemm_tc_kernel<0><<<dim3(KVI / 128, T_LEN / 128), 256, GSMEM>>>(
        xh, xl, wkh, wkl, pk, nullptr, nullptr, KVI, INNER);
    gemm_tc_kernel<2><<<dim3(KVI / 128, T_LEN / 128), 256, GSMEM>>>(
        xh, xl, wvh, wvl, nullptr, vth, vtl, KVI, INNER);

    rope_kernel<<<T_LEN, 256>>>(pq, pk, qhp, qlp, khp, klp);

    attn_tc_kernel<<<dim3(T_LEN / 128, NH), 256, ATT_SMEM>>>(
        qhp, qlp, khp, klp, vth, vtl, aoh, aol);

    // O projection: cg2 as well
    gemm_tc_cg2_kernel<<<dim3((T_LEN / 256) * 2, INNER / 128), 256, C2_SMEM>>>(
        aoh, aol, woh, wol, out, INNER, INNER);
}

// round 10
// speedup vs baseline: 1.3849x; 1.2892x over previous
#include <cuda_runtime.h>
#include <cuda_bf16.h>
#include <math.h>
#include <cstdint>
#include <cstddef>

// Problem constants
#define T_LEN 2048
#define NH    32
#define HKV   8
#define HD    128
#define INNER 4096      // NH*HD
#define KVI   1024      // HKV*HD

// tcgen05 only exists in the compute_103a pass; the plain compute_103 JIT
// fallback pass compiles these as stubs (never executed on GB300).
#if defined(__CUDA_ARCH_FEAT_SM103_ALL) || defined(__CUDA_ARCH_FEAT_SM100_ALL)
#define TC_OK 1
#else
#define TC_OK 0
#endif

// ---------------------------------------------------------------------------
// Scratch (device globals: no allocation allowed)
// ---------------------------------------------------------------------------
__device__ __nv_bfloat16 g_xh [T_LEN * INNER], g_xl [T_LEN * INNER];
__device__ __nv_bfloat16 g_wqh[INNER * INNER], g_wql[INNER * INNER];
__device__ __nv_bfloat16 g_wkh[KVI  * INNER], g_wkl[KVI  * INNER];
__device__ __nv_bfloat16 g_wvh[KVI  * INNER], g_wvl[KVI  * INNER];
__device__ __nv_bfloat16 g_woh[INNER * INNER], g_wol[INNER * INNER];

__device__ __nv_bfloat16 g_qh [T_LEN * INNER], g_ql [T_LEN * INNER];
__device__ __nv_bfloat16 g_kh [T_LEN * KVI],  g_kl [T_LEN * KVI];
__device__ __nv_bfloat16 g_vth[KVI * T_LEN],  g_vtl[KVI * T_LEN];   // V^T [dim][t]
__device__ __nv_bfloat16 g_aoh[T_LEN * INNER], g_aol[T_LEN * INNER];

// ---------------------------------------------------------------------------
// PTX helpers (sm_103a)
// ---------------------------------------------------------------------------
static __device__ __forceinline__ uint32_t s2u(const void* p) {
    uint32_t a;
    asm("{ .reg .u64 t; cvta.to.shared.u64 t, %1; cvt.u32.u64 %0, t; }"
        : "=r"(a) : "l"(p));
    return a;
}
static __device__ __forceinline__ uint32_t elect1() {
    uint32_t p;
    asm volatile("{ .reg .pred p; elect.sync _|p, 0xFFFFFFFF; selp.b32 %0,1,0,p; }"
                 : "=r"(p));
    return p;
}
static __device__ __forceinline__ void mbar_init(uint32_t a, uint32_t n) {
    asm volatile("mbarrier.init.shared.b64 [%0], %1;" :: "r"(a), "r"(n) : "memory");
}
static __device__ __forceinline__ void mbar_wait(uint32_t a, uint32_t par) {
    asm volatile(
        "{\n\t.reg .pred P;\n\t"
        "LAB%=:\n\t"
        "mbarrier.try_wait.parity.acquire.cta.shared::cta.b64 P, [%0], %1, 0x989680;\n\t"
        "@P bra DONE%=;\n\t"
        "bra LAB%=;\n\t"
        "DONE%=:\n\t}"
        :: "r"(a), "r"(par) : "memory");
}
static __device__ __forceinline__ void tc_alloc(uint32_t smem_addr, uint32_t ncols) {
#if TC_OK
    asm volatile("tcgen05.alloc.cta_group::1.sync.aligned.shared::cta.b32 [%0], %1;"
                 :: "r"(smem_addr), "r"(ncols) : "memory");
#endif
}
static __device__ __forceinline__ void tc_relinq() {
#if TC_OK
    asm volatile("tcgen05.relinquish_alloc_permit.cta_group::1.sync.aligned;");
#endif
}
static __device__ __forceinline__ void tc_dealloc(uint32_t tmem, uint32_t ncols) {
#if TC_OK
    asm volatile("tcgen05.dealloc.cta_group::1.sync.aligned.b32 %0, %1;"
                 :: "r"(tmem), "r"(ncols));
#endif
}
static __device__ __forceinline__ void tc_commit(uint32_t mbar) {
#if TC_OK
    asm volatile("tcgen05.commit.cta_group::1.mbarrier::arrive::one.shared::cluster.b64 [%0];"
                 :: "r"(mbar) : "memory");
#endif
}
static __device__ __forceinline__ void tc_mma_f16_ss(uint32_t d, uint64_t ad, uint64_t bd,
                                                     uint32_t idesc, uint32_t en) {
#if TC_OK
    asm volatile(
        "{\n\t.reg .pred p;\n\t"
        "setp.ne.u32 p, %4, 0;\n\t"
        "tcgen05.mma.cta_group::1.kind::f16 [%0], %1, %2, %3, {%5,%5,%5,%5}, p;\n\t}"
        :: "r"(d), "l"(ad), "l"(bd), "r"(idesc), "r"(en), "r"(0u) : "memory");
#endif
}
static __device__ __forceinline__ void tc_mma_f16_ts(uint32_t d, uint32_t a, uint64_t bd,
                                                     uint32_t idesc, uint32_t en) {
#if TC_OK
    asm volatile(
        "{\n\t.reg .pred p;\n\t"
        "setp.ne.u32 p, %4, 0;\n\t"
        "tcgen05.mma.cta_group::1.kind::f16 [%0], [%1], %2, %3, {%5,%5,%5,%5}, p;\n\t}"
        :: "r"(d), "r"(a), "l"(bd), "r"(idesc), "r"(en), "r"(0u) : "memory");
#endif
}
static __device__ __forceinline__ void tc_waitld() {
#if TC_OK
    asm volatile("tcgen05.wait::ld.sync.aligned;" ::: "memory");
#endif
}
static __device__ __forceinline__ void tc_waitst() {
#if TC_OK
    asm volatile("tcgen05.wait::st.sync.aligned;" ::: "memory");
#endif
}
static __device__ __forceinline__ void tc_fence_after() {
#if TC_OK
    asm volatile("tcgen05.fence::after_thread_sync;" ::: "memory");
#endif
}
static __device__ __forceinline__ void tc_fence_before() {
#if TC_OK
    asm volatile("tcgen05.fence::before_thread_sync;" ::: "memory");
#endif
}
static __device__ __forceinline__ void fence_async() {
    asm volatile("fence.proxy.async.shared::cta;" ::: "memory");
}
static __device__ __forceinline__ void tc_ld32(uint32_t* r, uint32_t ta) {
#if TC_OK
    asm volatile(
        "tcgen05.ld.sync.aligned.32x32b.x32.b32 "
        "{%0, %1, %2, %3, %4, %5, %6, %7, "
        " %8, %9, %10, %11, %12, %13, %14, %15, "
        " %16, %17, %18, %19, %20, %21, %22, %23, "
        " %24, %25, %26, %27, %28, %29, %30, %31}, [%32];"
        : "=r"(r[0]),  "=r"(r[1]),  "=r"(r[2]),  "=r"(r[3]),
          "=r"(r[4]),  "=r"(r[5]),  "=r"(r[6]),  "=r"(r[7]),
          "=r"(r[8]),  "=r"(r[9]),  "=r"(r[10]), "=r"(r[11]),
          "=r"(r[12]), "=r"(r[13]), "=r"(r[14]), "=r"(r[15]),
          "=r"(r[16]), "=r"(r[17]), "=r"(r[18]), "=r"(r[19]),
          "=r"(r[20]), "=r"(r[21]), "=r"(r[22]), "=r"(r[23]),
          "=r"(r[24]), "=r"(r[25]), "=r"(r[26]), "=r"(r[27]),
          "=r"(r[28]), "=r"(r[29]), "=r"(r[30]), "=r"(r[31])
        : "r"(ta));
#else
    for (int i = 0; i < 32; i++) r[i] = 0u;
    (void)ta;
#endif
}
static __device__ __forceinline__ void tc_st16(uint32_t ta, const uint32_t* r) {
#if TC_OK
    asm volatile(
        "tcgen05.st.sync.aligned.32x32b.x16.b32 [%0], "
        "{%1, %2, %3, %4, %5, %6, %7, %8, "
        " %9, %10, %11, %12, %13, %14, %15, %16};"
        :: "r"(ta),
           "r"(r[0]),  "r"(r[1]),  "r"(r[2]),  "r"(r[3]),
           "r"(r[4]),  "r"(r[5]),  "r"(r[6]),  "r"(r[7]),
           "r"(r[8]),  "r"(r[9]),  "r"(r[10]), "r"(r[11]),
           "r"(r[12]), "r"(r[13]), "r"(r[14]), "r"(r[15])
        : "memory");
#else
    (void)ta; (void)r;
#endif
}
static __device__ __forceinline__ uint64_t mk_desc(uint32_t addr) {
    // K-major SW128: LBO=1 (16B), SBO=64 (1024B / 8-row atom)
    const uint64_t BASE = (2ull << 61) | (1ull << 46) | (64ull << 32) | (1ull << 16);
    return BASE | ((uint64_t)(addr >> 4) & 0x3FFF);
}
static __device__ __forceinline__ void cp16(uint32_t dst, const void* src) {
    asm volatile("cp.async.cg.shared.global [%0], [%1], 16;"
                 :: "r"(dst), "l"(src) : "memory");
}
static __device__ __forceinline__ void cp_commit() {
    asm volatile("cp.async.commit_group;" ::: "memory");
}
static __device__ __forceinline__ void cp_wait1() {
    asm volatile("cp.async.wait_group 1;" ::: "memory");
}
static __device__ __forceinline__ void cp_wait0() {
    asm volatile("cp.async.wait_group 0;" ::: "memory");
}
static __device__ __forceinline__ uint32_t pk2(__nv_bfloat16 a, __nv_bfloat16 b) {
    __nv_bfloat162 t(a, b);
    return *(uint32_t*)&t;
}

// ---------------------------------------------------------------------------
// fp32 -> (bf16 hi, bf16 lo)
// ---------------------------------------------------------------------------
__global__ __launch_bounds__(256) void split_kernel(
    const float* __restrict__ in, __nv_bfloat16* __restrict__ hi,
    __nv_bfloat16* __restrict__ lo, int n)
{
    int stride = gridDim.x * blockDim.x * 4;
    for (int i = (blockIdx.x * blockDim.x + threadIdx.x) * 4; i < n; i += stride) {
        float4 x = *(const float4*)(in + i);
        __nv_bfloat16 h0 = __float2bfloat16(x.x);
        __nv_bfloat16 h1 = __float2bfloat16(x.y);
        __nv_bfloat16 h2 = __float2bfloat16(x.z);
        __nv_bfloat16 h3 = __float2bfloat16(x.w);
        __nv_bfloat16 l0 = __float2bfloat16(x.x - __bfloat162float(h0));
        __nv_bfloat16 l1 = __float2bfloat16(x.y - __bfloat162float(h1));
        __nv_bfloat16 l2 = __float2bfloat16(x.z - __bfloat162float(h2));
        __nv_bfloat16 l3 = __float2bfloat16(x.w - __bfloat162float(h3));
        __nv_bfloat162* hp = (__nv_bfloat162*)(hi + i);
        __nv_bfloat162* lp = (__nv_bfloat162*)(lo + i);
        hp[0] = __nv_bfloat162(h0, h1); hp[1] = __nv_bfloat162(h2, h3);
        lp[0] = __nv_bfloat162(l0, l1); lp[1] = __nv_bfloat162(l2, l3);
    }
}

// ---------------------------------------------------------------------------
// Common GEMM geometry (round-6/7 verified 128x128 3-stage pipeline)
// ---------------------------------------------------------------------------
#define GCHUNK   64
#define GTILE_B  16384
#define GSTAGE_B (4 * GTILE_B)          // 65536
#define GCTRL    (3 * GSTAGE_B)         // 196608
#define GSMEM    (GCTRL + 64)
#define GSMEM_U  (GCTRL + 64 + 256)     // + inv-freq table (proj kernel)

// ---------------------------------------------------------------------------
// Unified Q/K/V projection: verified 128x128 bf16x3 GEMM body; blockIdx.x
// selects output (0..31 Q, 32..39 K, 40..47 V). Q/K epilogues apply RoPE
// (bit-identical formula to the old rope_kernel) + pre-scale + bf16 hi/lo
// split in-register. V epilogue writes the transposed V^T hi/lo (verified).
// ---------------------------------------------------------------------------
__global__ __launch_bounds__(256) void proj_qkv_kernel(
    const __nv_bfloat16* __restrict__ Ah, const __nv_bfloat16* __restrict__ Al,
    const __nv_bfloat16* __restrict__ wqh, const __nv_bfloat16* __restrict__ wql,
    const __nv_bfloat16* __restrict__ wkh, const __nv_bfloat16* __restrict__ wkl,
    const __nv_bfloat16* __restrict__ wvh, const __nv_bfloat16* __restrict__ wvl,
    __nv_bfloat16* __restrict__ qh, __nv_bfloat16* __restrict__ ql,
    __nv_bfloat16* __restrict__ kh, __nv_bfloat16* __restrict__ kl,
    __nv_bfloat16* __restrict__ vth, __nv_bfloat16* __restrict__ vtl)
{
    extern __shared__ char sm_raw[];
    const uint32_t sb  = s2u(sm_raw);
    const int tid = threadIdx.x;
    const int wid = tid >> 5;
    const int m0  = blockIdx.y * 128;
    const int bx  = blockIdx.x;
    const int mode = (bx < 32) ? 0 : ((bx < 40) ? 1 : 2);  // Q / K / V
    const int n0   = ((mode == 0) ? bx : ((mode == 1) ? bx - 32 : bx - 40)) * 128;
    const __nv_bfloat16* Bh = (mode == 0) ? wqh : ((mode == 1) ? wkh : wvh);
    const __nv_bfloat16* Bl = (mode == 0) ? wql : ((mode == 1) ? wkl : wvl);

    float* sInv = (float*)(sm_raw + GCTRL + 64);
    if (tid < 64)
        sInv[tid] = (float)exp2(-(double)tid * 0.20762050593045952); // log2(1e4)/64

    if (wid == 0) { tc_alloc(sb + GCTRL + 32, 128); tc_relinq(); }
    if (tid == 0) {
        mbar_init(sb + GCTRL + 0, 1);
        mbar_init(sb + GCTRL + 8, 1);
        mbar_init(sb + GCTRL + 16, 1);
    }
    __syncthreads();
    uint32_t tmem;
    asm volatile("ld.shared.b32 %0, [%1];" : "=r"(tmem) : "r"(sb + GCTRL + 32));

    const uint32_t idesc = (1u << 4) | (1u << 7) | (1u << 10) |
                           ((128u / 8) << 17) | ((128u / 16) << 24);

    const int K  = INNER;
    const int KW = K >> 3;
    const int g  = tid & 7;
    const int rb = tid >> 3;            // 0..31
    const int sc = g ^ (rb & 7);
    const size_t a4 = (((size_t)(m0 + rb) * K) >> 3) + g;
    const size_t b4 = (((size_t)(n0 + rb) * K) >> 3) + g;
    const uint4* srcs[4] = { (const uint4*)Ah, (const uint4*)Al,
                             (const uint4*)Bh, (const uint4*)Bl };
    const uint32_t dbase = sb + (rb * 8 + sc) * 16;

    const int NCH = K / GCHUNK;         // 64

    auto load_chunk = [&](int c, int s) {
        const size_t ko4 = (size_t)c * 8;
#pragma unroll
        for (int t = 0; t < 4; t++) {
            const size_t base = ((t < 2) ? a4 : b4) + ko4;
            const uint4* sp = srcs[t];
            const uint32_t d0 = dbase + s * GSTAGE_B + t * GTILE_B;
#pragma unroll
            for (int r = 0; r < 4; r++)
                cp16(d0 + r * 32 * 128, sp + base + (size_t)(32 * r) * KW);
        }
        cp_commit();
    };

    load_chunk(0, 0);
    load_chunk(1, 1);

    int par[3] = {0, 0, 0};
    for (int c = 0; c < NCH; c++) {
        const int s = c % 3;
        if (c == NCH - 1) cp_wait0(); else cp_wait1();
        __syncthreads();
        if (wid == 0 && elect1()) {
            fence_async();
            tc_fence_after();
            const uint32_t sa = sb + s * GSTAGE_B;
            const uint64_t dAh = mk_desc(sa);
            const uint64_t dAl = mk_desc(sa + GTILE_B);
            const uint64_t dBh = mk_desc(sa + 2 * GTILE_B);
            const uint64_t dBl = mk_desc(sa + 3 * GTILE_B);
#pragma unroll
            for (int ks = 0; ks < 4; ks++)
                tc_mma_f16_ss(tmem, dAh + ks * 2, dBh + ks * 2, idesc,
                              (c == 0 && ks == 0) ? 0u : 1u);
#pragma unroll
            for (int ks = 0; ks < 4; ks++)
                tc_mma_f16_ss(tmem, dAh + ks * 2, dBl + ks * 2, idesc, 1u);
#pragma unroll
            for (int ks = 0; ks < 4; ks++)
                tc_mma_f16_ss(tmem, dAl + ks * 2, dBh + ks * 2, idesc, 1u);
            tc_commit(sb + GCTRL + s * 8);
        }
        if (c + 2 < NCH) {
            if (c >= 1) {
                int ws = (c - 1) % 3;
                mbar_wait(sb + GCTRL + ws * 8, par[ws]);
                par[ws] ^= 1;
            }
            load_chunk(c + 2, (c + 2) % 3);
        }
    }

    {   // wait for the final chunk's MMAs
        int sl = (NCH - 1) % 3;
        int q  = (NCH - 1 - sl) / 3 + 1;
        mbar_wait(sb + GCTRL + sl * 8, (q - 1) & 1);
    }
    tc_fence_after();

    if (tid < 128) {
        if (mode == 2) {
            // V: transposed bf16 hi/lo (verified round-7 epilogue)
#pragma unroll
            for (int cb = 0; cb < 4; cb++) {
                uint32_t dr[32];
                tc_ld32(dr, tmem + cb * 32);
                tc_waitld();
#pragma unroll
                for (int j = 0; j < 32; j++) {
                    float f = __uint_as_float(dr[j]);
                    __nv_bfloat16 hv = __float2bfloat16(f);
                    __nv_bfloat16 lv = __float2bfloat16(f - __bfloat162float(hv));
                    size_t idx = (size_t)(n0 + cb * 32 + j) * T_LEN + m0 + tid;
                    vth[idx] = hv;
                    vtl[idx] = lv;
                }
            }
        } else {
            // Q/K: gather full row (one complete head), RoPE in-place,
            // pre-scale (Q only), bf16 hi/lo split.
            float buf[128];
#pragma unroll
            for (int cb = 0; cb < 4; cb++) {
                uint32_t dr[32];
                tc_ld32(dr, tmem + cb * 32);
                tc_waitld();
#pragma unroll
                for (int j = 0; j < 32; j++) buf[cb * 32 + j] = __uint_as_float(dr[j]);
            }
            const int   t   = m0 + tid;
            const float sc2 = (mode == 0) ? 0.08838834764831845f : 1.0f;
#pragma unroll
            for (int d = 0; d < 64; d++) {
                float ang = (float)t * sInv[d];
                float s, c;
                sincosf(ang, &s, &c);
                float x1 = buf[d], x2 = buf[d + 64];
                buf[d]      = (x1 * c - x2 * s) * sc2;
                buf[d + 64] = (x2 * c + x1 * s) * sc2;
            }
            const size_t stride = (mode == 0) ? INNER : KVI;
            __nv_bfloat16* oh = ((mode == 0) ? qh : kh) + (size_t)t * stride + n0;
            __nv_bfloat16* ol = ((mode == 0) ? ql : kl) + (size_t)t * stride + n0;
#pragma unroll
            for (int blk = 0; blk < 16; blk++) {
                uint32_t H[2], L[2];
#pragma unroll
                for (int m = 0; m < 2; m++) {
                    float f0 = buf[blk * 8 + 2 * m * 2 + 0];   // careful: pack pairs
                    (void)f0;
                }
                // pack 8 consecutive values -> 4 hi words + 4 lo words
                uint32_t Hw[4], Lw[4];
#pragma unroll
                for (int m = 0; m < 4; m++) {
                    float f0 = buf[blk * 8 + 2 * m];
                    float f1 = buf[blk * 8 + 2 * m + 1];
                    __nv_bfloat16 h0 = __float2bfloat16(f0);
                    __nv_bfloat16 h1 = __float2bfloat16(f1);
                    __nv_bfloat16 l0 = __float2bfloat16(f0 - __bfloat162float(h0));
                    __nv_bfloat16 l1 = __float2bfloat16(f1 - __bfloat162float(h1));
                    Hw[m] = pk2(h0, h1);
                    Lw[m] = pk2(l0, l1);
                }
                *(uint4*)(oh + blk * 8) = *(uint4*)Hw;
                *(uint4*)(ol + blk * 8) = *(uint4*)Lw;
                (void)H; (void)L;
            }
        }
        tc_fence_before();
    }
    __syncthreads();
    if (wid == 0) tc_dealloc(tmem, 128);
}

// ---------------------------------------------------------------------------
// O-projection GEMM (round-6/7 verified, fp32 out).
// ---------------------------------------------------------------------------
__global__ __launch_bounds__(256) void gemm_tc_kernel(
    const __nv_bfloat16* __restrict__ Ah, const __nv_bfloat16* __restrict__ Al,
    const __nv_bfloat16* __restrict__ Bh, const __nv_bfloat16* __restrict__ Bl,
    float* __restrict__ C, int N, int K)
{
    extern __shared__ char sm_raw[];
    const uint32_t sb  = s2u(sm_raw);
    const int tid = threadIdx.x;
    const int wid = tid >> 5;
    const int m0  = blockIdx.y * 128;
    const int n0  = blockIdx.x * 128;

    if (wid == 0) { tc_alloc(sb + GCTRL + 32, 128); tc_relinq(); }
    if (tid == 0) {
        mbar_init(sb + GCTRL + 0, 1);
        mbar_init(sb + GCTRL + 8, 1);
        mbar_init(sb + GCTRL + 16, 1);
    }
    __syncthreads();
    uint32_t tmem;
    asm volatile("ld.shared.b32 %0, [%1];" : "=r"(tmem) : "r"(sb + GCTRL + 32));

    const uint32_t idesc = (1u << 4) | (1u << 7) | (1u << 10) |
                           ((128u / 8) << 17) | ((128u / 16) << 24);

    const int KW = K >> 3;
    const int g  = tid & 7;
    const int rb = tid >> 3;
    const int sc = g ^ (rb & 7);
    const size_t a4 = (((size_t)(m0 + rb) * K) >> 3) + g;
    const size_t b4 = (((size_t)(n0 + rb) * K) >> 3) + g;
    const uint4* srcs[4] = { (const uint4*)Ah, (const uint4*)Al,
                             (const uint4*)Bh, (const uint4*)Bl };
    const uint32_t dbase = sb + (rb * 8 + sc) * 16;

    const int NCH = K / GCHUNK;

    auto load_chunk = [&](int c, int s) {
        const size_t ko4 = (size_t)c * 8;
#pragma unroll
        for (int t = 0; t < 4; t++) {
            const size_t base = ((t < 2) ? a4 : b4) + ko4;
            const uint4* sp = srcs[t];
            const uint32_t d0 = dbase + s * GSTAGE_B + t * GTILE_B;
#pragma unroll
            for (int r = 0; r < 4; r++)
                cp16(d0 + r * 32 * 128, sp + base + (size_t)(32 * r) * KW);
        }
        cp_commit();
    };

    load_chunk(0, 0);
    load_chunk(1, 1);

    int par[3] = {0, 0, 0};
    for (int c = 0; c < NCH; c++) {
        const int s = c % 3;
        if (c == NCH - 1) cp_wait0(); else cp_wait1();
        __syncthreads();
        if (wid == 0 && elect1()) {
            fence_async();
            tc_fence_after();
            const uint32_t sa = sb + s * GSTAGE_B;
            const uint64_t dAh = mk_desc(sa);
            const uint64_t dAl = mk_desc(sa + GTILE_B);
            const uint64_t dBh = mk_desc(sa + 2 * GTILE_B);
            const uint64_t dBl = mk_desc(sa + 3 * GTILE_B);
#pragma unroll
            for (int ks = 0; ks < 4; ks++)
                tc_mma_f16_ss(tmem, dAh + ks * 2, dBh + ks * 2, idesc,
                              (c == 0 && ks == 0) ? 0u : 1u);
#pragma unroll
            for (int ks = 0; ks < 4; ks++)
                tc_mma_f16_ss(tmem, dAh + ks * 2, dBl + ks * 2, idesc, 1u);
#pragma unroll
            for (int ks = 0; ks < 4; ks++)
                tc_mma_f16_ss(tmem, dAl + ks * 2, dBh + ks * 2, idesc, 1u);
            tc_commit(sb + GCTRL + s * 8);
        }
        if (c + 2 < NCH) {
            if (c >= 1) {
                int ws = (c - 1) % 3;
                mbar_wait(sb + GCTRL + ws * 8, par[ws]);
                par[ws] ^= 1;
            }
            load_chunk(c + 2, (c + 2) % 3);
        }
    }

    {
        int sl = (NCH - 1) % 3;
        int q  = (NCH - 1 - sl) / 3 + 1;
        mbar_wait(sb + GCTRL + sl * 8, (q - 1) & 1);
    }
    tc_fence_after();

    if (tid < 128) {
#pragma unroll
        for (int cb = 0; cb < 4; cb++) {
            uint32_t dr[32];
            tc_ld32(dr, tmem + cb * 32);
            tc_waitld();
            float* cp = C + (size_t)(m0 + tid) * N + n0 + cb * 32;
#pragma unroll
            for (int j = 0; j < 32; j += 4)
                *(float4*)(cp + j) = make_float4(
                    __uint_as_float(dr[j]), __uint_as_float(dr[j + 1]),
                    __uint_as_float(dr[j + 2]), __uint_as_float(dr[j + 3]));
        }
        tc_fence_before();
    }
    __syncthreads();
    if (wid == 0) tc_dealloc(tmem, 128);
}

// ---------------------------------------------------------------------------
// tcgen05 causal flash attention (round-7 verified, unchanged).
// ---------------------------------------------------------------------------
#define ATT_Q    0
#define ATT_K    65536
#define ATT_V    131072
#define ATT_CTRL 196608
#define ATT_SMEM (ATT_CTRL + 64)

__global__ __launch_bounds__(256) void attn_tc_kernel(
    const __nv_bfloat16* __restrict__ qh, const __nv_bfloat16* __restrict__ ql,
    const __nv_bfloat16* __restrict__ kh, const __nv_bfloat16* __restrict__ kl,
    const __nv_bfloat16* __restrict__ vth, const __nv_bfloat16* __restrict__ vtl,
    __nv_bfloat16* __restrict__ aoh, __nv_bfloat16* __restrict__ aol)
{
    extern __shared__ char sm_raw[];
    const uint32_t sb = s2u(sm_raw);
    const int tid  = threadIdx.x;
    const int wid  = tid >> 5;
    const int lane = tid & 31;
    const int h    = blockIdx.y;
    const int qb   = gridDim.x - 1 - blockIdx.x;   // heavy tiles first
    const int hk   = h >> 2;
    const int q0   = qb * 128;

    const uint32_t mbarS  = sb + ATT_CTRL + 0;
    const uint32_t mbarPV = sb + ATT_CTRL + 8;

    if (wid == 0) { tc_alloc(sb + ATT_CTRL + 16, 512); tc_relinq(); }
    if (tid == 0) { mbar_init(mbarS, 1); mbar_init(mbarPV, 1); }
    __syncthreads();
    uint32_t tmem;
    asm volatile("ld.shared.b32 %0, [%1];" : "=r"(tmem) : "r"(sb + ATT_CTRL + 16));
    const uint32_t TM_S = tmem, TM_O = tmem + 128, TM_PH = tmem + 256,
                   TM_PL = tmem + 320;

    const uint32_t idescS  = (1u << 4) | (1u << 7) | (1u << 10) |
                             (16u << 17) | (8u << 24);   // M128 N128
    const uint32_t idescPV = (1u << 4) | (1u << 7) | (1u << 10) |
                             (8u << 17) | (8u << 24);    // M128 N64

    const int g   = tid & 7;
    const int rb  = tid >> 3;               // 0..31
    const int sub = wid & 3;                // TMEM subpartition
    const int cgp = wid >> 2;               // column group
    const int rloc = sub * 32 + lane;       // q row within tile

    // ---- Q tile (persistent), cp.async group: {QH c0, QH c1, QL c0, QL c1}
    {
        const size_t qrow4 = ((size_t)q0 * INNER + h * HD) >> 3;
#pragma unroll
        for (int st = 0; st < 4; st++) {
            const uint4* sp = (const uint4*)((st < 2) ? qh : ql);
            const int c = st & 1;
#pragma unroll
            for (int r = 0; r < 4; r++) {
                int row = rb + 32 * r;
                cp16(sb + ATT_Q + st * 16384 + (row * 8 + (g ^ (row & 7))) * 16,
                     sp + qrow4 + (size_t)row * (INNER / 8) + c * 8 + g);
            }
        }
        cp_commit();
    }

    float l_acc = 0.f;
    int parS = 0, parPV = 0;

    for (int kt = 0; kt <= qb; kt++) {
        const int k0 = kt * 128;
        // ---- K tile cp.async
        {
            const size_t krow4 = ((size_t)k0 * KVI + hk * HD) >> 3;
#pragma unroll
            for (int st = 0; st < 4; st++) {
                const uint4* sp = (const uint4*)((st < 2) ? kh : kl);
                const int c = st & 1;
#pragma unroll
                for (int r = 0; r < 4; r++) {
                    int row = rb + 32 * r;
                    cp16(sb + ATT_K + st * 16384 + (row * 8 + (g ^ (row & 7))) * 16,
                         sp + krow4 + (size_t)row * (KVI / 8) + c * 8 + g);
                }
            }
            cp_commit();
        }
        // ---- PV(kt-1) must finish before sV overwrite / P TMEM overwrite
        if (kt > 0) { mbar_wait(mbarPV, parPV); parPV ^= 1; }
        // ---- V^T tile cp.async: 8 subtiles [64 dims][64 keys] K-major
        {
#pragma unroll
            for (int st = 0; st < 8; st++) {
                const int hl = st >> 2, hf = (st >> 1) & 1, c = st & 1;
                const uint4* sp = (const uint4*)(hl ? vtl : vth);
                const size_t base4 =
                    (((size_t)(hk * 128 + hf * 64)) * T_LEN + k0 + c * 64) >> 3;
#pragma unroll
                for (int r = 0; r < 2; r++) {
                    int row = rb + 32 * r;
                    cp16(sb + ATT_V + st * 8192 + (row * 8 + (g ^ (row & 7))) * 16,
                         sp + base4 + (size_t)row * (T_LEN / 8) + g);
                }
            }
            cp_commit();
        }
        cp_wait1();                 // Q (first iter) + K complete; V may fly
        __syncthreads();
        // ---- S = Q' K^T (3 bf16 passes, SS K-major)
        if (wid == 0 && elect1()) {
            fence_async();
            tc_fence_after();
            uint64_t dQ[4], dK[4];
#pragma unroll
            for (int st = 0; st < 4; st++) {
                dQ[st] = mk_desc(sb + ATT_Q + st * 16384);
                dK[st] = mk_desc(sb + ATT_K + st * 16384);
            }
#pragma unroll
            for (int p = 0; p < 3; p++) {
                const int ai = (p < 2) ? 0 : 2;
                const int bi = (p == 1) ? 2 : 0;
#pragma unroll
                for (int c = 0; c < 2; c++)
#pragma unroll
                    for (int ks = 0; ks < 4; ks++)
                        tc_mma_f16_ss(TM_S, dQ[ai + c] + ks * 2, dK[bi + c] + ks * 2,
                                      idescS, (p == 0 && c == 0 && ks == 0) ? 0u : 1u);
            }
            tc_commit(mbarS);
        }
        // ---- wait S, softmax epilogue (8 warps, 2 col-chunks each)
        mbar_wait(mbarS, parS); parS ^= 1;
        tc_fence_after();
#pragma unroll
        for (int cc = 0; cc < 2; cc++) {
            const int cb = cgp * 2 + cc;
            uint32_t sr[32];
            tc_ld32(sr, TM_S + cb * 32);
            tc_waitld();
            float pr[32];
#pragma unroll
            for (int j = 0; j < 32; j++) {
                float s = __uint_as_float(sr[j]);
                int key = k0 + cb * 32 + j;
                float p = __expf(s - 8.0f);
                if (kt == qb && key > q0 + rloc) p = 0.f;
                pr[j] = p;
                l_acc += p;
            }
            uint32_t ph[16], pl[16];
#pragma unroll
            for (int m = 0; m < 16; m++) {
                float f0 = pr[2 * m], f1 = pr[2 * m + 1];
                __nv_bfloat16 h0 = __float2bfloat16(f0);
                __nv_bfloat16 h1 = __float2bfloat16(f1);
                __nv_bfloat16 l0 = __float2bfloat16(f0 - __bfloat162float(h0));
                __nv_bfloat16 l1 = __float2bfloat16(f1 - __bfloat162float(h1));
                ph[m] = pk2(h0, h1);
                pl[m] = pk2(l0, l1);
            }
            tc_st16(TM_PH + cb * 16 + ((uint32_t)sub << 21), ph);
            tc_st16(TM_PL + cb * 16 + ((uint32_t)sub << 21), pl);
        }
        tc_waitst();
        tc_fence_before();
        cp_wait0();                  // V tiles complete
        __syncthreads();             // P in TMEM + V in smem visible
        // ---- O += P V (TS-mode, K-major V^T subtiles)
        if (wid == 0 && elect1()) {
            fence_async();
            tc_fence_after();
            uint64_t dV[8];
#pragma unroll
            for (int st = 0; st < 8; st++)
                dV[st] = mk_desc(sb + ATT_V + st * 8192);
#pragma unroll
            for (int hf = 0; hf < 2; hf++) {
                const uint32_t D = TM_O + hf * 64;
#pragma unroll
                for (int p = 0; p < 3; p++) {
                    const uint32_t A = (p == 2) ? TM_PL : TM_PH;
                    const int hl = (p == 1) ? 1 : 0;
#pragma unroll
                    for (int c = 0; c < 2; c++)
#pragma unroll
                        for (int ks = 0; ks < 4; ks++)
                            tc_mma_f16_ts(D, A + 32 * c + ks * 8,
                                          dV[(hl * 2 + hf) * 2 + c] + ks * 2,
                                          idescPV,
                                          (kt == 0 && p == 0 && c == 0 && ks == 0)
                                              ? 0u : 1u);
                }
            }
            tc_commit(mbarPV);
        }
    }

    mbar_wait(mbarPV, parPV);
    tc_fence_after();

    // combine l across the two warp-groups (sK area is free)
    float* lbuf = (float*)(sm_raw + ATT_K);
    lbuf[cgp * 128 + rloc] = l_acc;
    __syncthreads();
    const float linv = 1.f / (lbuf[rloc] + lbuf[128 + rloc]);

    // O epilogue: normalize + bf16 hi/lo split
#pragma unroll
    for (int cc = 0; cc < 2; cc++) {
        const int cb = cgp * 2 + cc;
        uint32_t orr[32];
        tc_ld32(orr, TM_O + cb * 32);
        tc_waitld();
        uint32_t hv[16], lv[16];
#pragma unroll
        for (int m = 0; m < 16; m++) {
            float f0 = __uint_as_float(orr[2 * m]) * linv;
            float f1 = __uint_as_float(orr[2 * m + 1]) * linv;
            __nv_bfloat16 h0 = __float2bfloat16(f0);
            __nv_bfloat16 h1 = __float2bfloat16(f1);
            __nv_bfloat16 l0 = __float2bfloat16(f0 - __bfloat162float(h0));
            __nv_bfloat16 l1 = __float2bfloat16(f1 - __bfloat162float(h1));
            hv[m] = pk2(h0, h1);
            lv[m] = pk2(l0, l1);
        }
        uint4* hq = (uint4*)(aoh + (size_t)(q0 + rloc) * INNER + h * HD + cb * 32);
        uint4* lq = (uint4*)(aol + (size_t)(q0 + rloc) * INNER + h * HD + cb * 32);
#pragma unroll
        for (int m = 0; m < 4; m++) {
            hq[m] = *(uint4*)&hv[4 * m];
            lq[m] = *(uint4*)&lv[4 * m];
        }
    }
    tc_fence_before();
    __syncthreads();
    if (wid == 0) tc_dealloc(tmem, 512);
}

// ---------------------------------------------------------------------------
extern "C" void kernel_launch(void* const* d_in, const int* in_sizes, int n_in,
                              void* d_out, int out_size)
{
    (void)in_sizes; (void)n_in; (void)out_size;
    const float* stm = (const float*)d_in[0];
    const float* w_q = (const float*)d_in[1];
    const float* w_k = (const float*)d_in[2];
    const float* w_v = (const float*)d_in[3];
    const float* w_o = (const float*)d_in[4];
    float* out = (float*)d_out;

    __nv_bfloat16 *xh, *xl, *wqh, *wql, *wkh, *wkl, *wvh, *wvl, *woh, *wol;
    __nv_bfloat16 *qhp, *qlp, *khp, *klp, *vth, *vtl, *aoh, *aol;
    cudaGetSymbolAddress((void**)&xh,  g_xh);  cudaGetSymbolAddress((void**)&xl,  g_xl);
    cudaGetSymbolAddress((void**)&wqh, g_wqh); cudaGetSymbolAddress((void**)&wql, g_wql);
    cudaGetSymbolAddress((void**)&wkh, g_wkh); cudaGetSymbolAddress((void**)&wkl, g_wkl);
    cudaGetSymbolAddress((void**)&wvh, g_wvh); cudaGetSymbolAddress((void**)&wvl, g_wvl);
    cudaGetSymbolAddress((void**)&woh, g_woh); cudaGetSymbolAddress((void**)&wol, g_wol);
    cudaGetSymbolAddress((void**)&qhp, g_qh);  cudaGetSymbolAddress((void**)&qlp, g_ql);
    cudaGetSymbolAddress((void**)&khp, g_kh);  cudaGetSymbolAddress((void**)&klp, g_kl);
    cudaGetSymbolAddress((void**)&vth, g_vth); cudaGetSymbolAddress((void**)&vtl, g_vtl);
    cudaGetSymbolAddress((void**)&aoh, g_aoh); cudaGetSymbolAddress((void**)&aol, g_aol);

    cudaFuncSetAttribute(proj_qkv_kernel,
                         cudaFuncAttributeMaxDynamicSharedMemorySize, GSMEM_U);
    cudaFuncSetAttribute(gemm_tc_kernel,
                         cudaFuncAttributeMaxDynamicSharedMemorySize, GSMEM);
    cudaFuncSetAttribute(attn_tc_kernel,
                         cudaFuncAttributeMaxDynamicSharedMemorySize, ATT_SMEM);

    split_kernel<<<4096, 256>>>(stm, xh,  xl,  T_LEN * INNER);
    split_kernel<<<4096, 256>>>(w_q, wqh, wql, INNER * INNER);
    split_kernel<<<4096, 256>>>(w_k, wkh, wkl, KVI * INNER);
    split_kernel<<<4096, 256>>>(w_v, wvh, wvl, KVI * INNER);
    split_kernel<<<4096, 256>>>(w_o, woh, wol, INNER * INNER);

    // Q + K + V projections fused in one launch; rope+split fused in epilogue
    proj_qkv_kernel<<<dim3(48, T_LEN / 128), 256, GSMEM_U>>>(
        xh, xl, wqh, wql, wkh, wkl, wvh, wvl,
        qhp, qlp, khp, klp, vth, vtl);

    attn_tc_kernel<<<dim3(T_LEN / 128, NH), 256, ATT_SMEM>>>(
        qhp, qlp, khp, klp, vth, vtl, aoh, aol);

    gemm_tc_kernel<<<dim3(INNER / 128, T_LEN / 128), 256, GSMEM>>>(
        aoh, aol, woh, wol, out, INNER, INNER);
}